// round 14
// baseline (speedup 1.0000x reference)
#include <cuda_runtime.h>
#include <cuda_fp16.h>
#include <math.h>
#include <stdint.h>

#define NN   20000
#define NP   20096      // 157 * 128
#define EE   640000
#define FIN  128
#define HH   128
#define TT   12
#define NOUT 64
#define GI   384
#define G4   512
#define MT   (TT * NP)  // 241152 batched rows

// ---------------- scratch ----------------
__device__ __half g_xh[(size_t)MT * FIN];        // x transposed+rounded, all t
__device__ __half g_g0[(size_t)MT * HH];         // upfront g0 per t
__device__ __half g_xw0[(size_t)MT * HH];        // upfront batched GCN out (fp16)
__device__ __half g_h0[3][(size_t)NP * HH];      // h0 triple buffer (mod 3)
__device__ __half g_h1[2][(size_t)NP * HH];      // h1 parity
__device__ float  g_c[2][(size_t)NP * HH];
__device__ float  g_hout[(size_t)NP * HH];
__device__ __half g_xw1[2][(size_t)NP * HH];     // in-loop gcn out, parity (fp16)
__device__ __half g_g1[2][(size_t)NP * HH];      // in-loop g, parity
__device__ __half g_Wt[2][G4 * GI];      // [pc=512][k=384] gate-interleaved, fp16
__device__ __half g_gwT[2][HH * HH];     // fp16
__device__ float  g_b4[2][G4];           // packed by pc
__device__ float g_deg[NN];
__device__ float g_dis[NN];
__device__ int   g_cnt[NN];
__device__ int   g_cur[NN];
__device__ int   g_ptr[NN + 1];
__device__ int   g_src[EE];
__device__ float g_wn[EE];

__device__ __forceinline__ float sigmoidf_(float x) { return 1.0f / (1.0f + expf(-x)); }
__device__ __forceinline__ uint32_t smem_u32(const void* p) {
    return (uint32_t)__cvta_generic_to_shared(p);
}
__device__ __forceinline__ uint32_t swz128(uint32_t o) { return o ^ ((o >> 3) & 0x70); }
__device__ __forceinline__ void cp16(uint32_t dst, const void* src) {
    asm volatile("cp.async.cg.shared.global [%0], [%1], 16;" :: "r"(dst), "l"(src));
}
__device__ __forceinline__ void ldm4(uint32_t* r, uint32_t addr) {
    asm volatile("ldmatrix.sync.aligned.m8n8.x4.shared.b16 {%0,%1,%2,%3}, [%4];"
                 : "=r"(r[0]), "=r"(r[1]), "=r"(r[2]), "=r"(r[3]) : "r"(addr));
}
__device__ __forceinline__ void mma16816(float* c, const uint32_t* a, const uint32_t* b) {
    asm volatile("mma.sync.aligned.m16n8k16.row.col.f32.f16.f16.f32 "
                 "{%0,%1,%2,%3}, {%4,%5,%6,%7}, {%8,%9}, {%0,%1,%2,%3};"
                 : "+f"(c[0]), "+f"(c[1]), "+f"(c[2]), "+f"(c[3])
                 : "r"(a[0]), "r"(a[1]), "r"(a[2]), "r"(a[3]), "r"(b[0]), "r"(b[1]));
}

// ---------------- graph preprocessing ----------------
__global__ void k_init_nodes() {
    int i = blockIdx.x * blockDim.x + threadIdx.x;
    if (i < NN) { g_deg[i] = 1.0f; g_cnt[i] = 0; }
}
__global__ void k_edge_deg(const float* __restrict__ ea, const int* __restrict__ ei) {
    int e = blockIdx.x * blockDim.x + threadIdx.x;
    if (e < EE) {
        int c = ei[EE + e];
        atomicAdd(&g_deg[c], ea[4 * e + 3]);
        atomicAdd(&g_cnt[c], 1);
    }
}
__global__ void k_node_prep() {
    int i = blockIdx.x * blockDim.x + threadIdx.x;
    if (i < NN) { g_dis[i] = rsqrtf(g_deg[i]); g_cur[i] = 0; }
}
__global__ void k_scan() {
    __shared__ int sh[2][1024];
    __shared__ int carry;
    int tid = threadIdx.x;
    if (tid == 0) carry = 0;
    __syncthreads();
    for (int base = 0; base < NN; base += 1024) {
        int v = (base + tid < NN) ? g_cnt[base + tid] : 0;
        int buf = 0;
        sh[0][tid] = v;
        __syncthreads();
        for (int off = 1; off < 1024; off <<= 1) {
            int val = sh[buf][tid];
            if (tid >= off) val += sh[buf][tid - off];
            sh[buf ^ 1][tid] = val;
            buf ^= 1;
            __syncthreads();
        }
        int incl = sh[buf][tid];
        int c0 = carry;
        if (base + tid < NN) g_ptr[base + tid] = c0 + incl - v;
        __syncthreads();
        if (tid == 1023) carry = c0 + sh[buf][1023];
        __syncthreads();
    }
    if (tid == 0) g_ptr[NN] = carry;
}
__global__ void k_edge_fill(const float* __restrict__ ea, const int* __restrict__ ei) {
    int e = blockIdx.x * blockDim.x + threadIdx.x;
    if (e < EE) {
        int r = ei[e];
        int c = ei[EE + e];
        float w = ea[4 * e + 3];
        int pos = g_ptr[c] + atomicAdd(&g_cur[c], 1);
        g_src[pos] = r;
        g_wn[pos]  = g_dis[r] * w * g_dis[c];
    }
}

// ---------------- input transpose (fp32 -> fp16) ----------------
__global__ void k_transpose(const float* __restrict__ x) {
    long nf = (long)blockIdx.x * blockDim.x + threadIdx.x;
    if (nf >= (long)NN * FIN) return;
    float v[TT];
#pragma unroll
    for (int t = 0; t < TT; t++) v[t] = x[nf * TT + t];
#pragma unroll
    for (int t = 0; t < TT; t++)
        g_xh[(long)t * NP * FIN + nf] = __float2half(v[t]);
}

// slices: s<TT: xh[t] pads; s<2TT: g0[t] pads; s=2TT,2TT+1: g1[parity] pads
__global__ void k_zero_pads() {
    const int padN = (NP - NN) * HH;   // 12288
    int i = blockIdx.x * blockDim.x + threadIdx.x;
    int s = i / padN, r = i % padN;
    if (s >= 2 * TT + 2) return;
    __half z = __float2half(0.0f);
    if (s < TT) {
        g_xh[(long)s * NP * FIN + (long)NN * FIN + r] = z;
    } else if (s < 2 * TT) {
        g_g0[(long)(s - TT) * NP * HH + (long)NN * HH + r] = z;
    } else {
        g_g1[s - 2 * TT][(long)NN * HH + r] = z;
    }
}

__global__ void k_zero_state() {
    long i = (long)blockIdx.x * blockDim.x + threadIdx.x;
    if (i < (long)NP * HH) {
        __half z = __float2half(0.0f);
        g_c[0][i] = 0.0f; g_c[1][i] = 0.0f;
#pragma unroll
        for (int p = 0; p < 3; p++) g_h0[p][i] = z;
#pragma unroll
        for (int p = 0; p < 2; p++) g_h1[p][i] = z;
    }
}

// ---------------- pack gate weights: pc = ((f>>3)<<5)|(g<<3)|(f&7) ----------------
__global__ void k_buildW(const float* __restrict__ wf, const float* __restrict__ wi,
                         const float* __restrict__ wo, const float* __restrict__ wc,
                         const float* __restrict__ bf, const float* __restrict__ bi,
                         const float* __restrict__ bo, const float* __restrict__ bc,
                         int layer) {
    int idx = blockIdx.x * blockDim.x + threadIdx.x;
    if (idx >= G4 * GI) return;
    int pc = idx / GI, k = idx % GI;
    int f = ((pc >> 5) << 3) | (pc & 7);
    int g = (pc >> 3) & 3;
    const float* w = (g == 0) ? wf : (g == 1) ? wi : (g == 2) ? wo : wc;
    g_Wt[layer][idx] = __float2half(w[k * 128 + f]);
    if (k == 0) {
        const float* b = (g == 0) ? bf : (g == 1) ? bi : (g == 2) ? bo : bc;
        g_b4[layer][pc] = b[f];
    }
}

__global__ void k_buildGW(const float* __restrict__ gw, int layer) {
    int idx = blockIdx.x * blockDim.x + threadIdx.x;
    if (idx >= HH * HH) return;
    int n = idx >> 7, k = idx & 127;
    g_gwT[layer][idx] = __float2half(gw[k * 128 + n]);
}

// ================= shared MMA mainloop =================
// 512 threads, 16 warps (4M x 4N of 32x32), tile 128x128, K chunks of 64.
// per-buffer layout: A 16K | B 16K (SW128 swizzled), single fp16 pass
#define BUFSZ 32768u
#define GATE_SMEM (3 * 32768)   // 3-stage
#define GCN_SMEM  (2 * 32768)   // 2-stage

struct Frag { float acc[2][4][4]; };

__device__ __forceinline__ void mma_chunk(uint32_t base, int m0, int n0, int lane, Frag& F) {
    int a_lr = ((lane >> 3) & 1) * 8 + (lane & 7);
    int a_cb = (lane >> 4) * 16;
    int b_lr = (lane >> 4) * 8 + (lane & 7);
    int b_cb = ((lane >> 3) & 1) * 16;
#pragma unroll
    for (int ks = 0; ks < 4; ks++) {
        int kb = ks * 32;
        uint32_t ah[2][4], bh[4][2];
#pragma unroll
        for (int mf = 0; mf < 2; mf++) {
            int row = m0 + mf * 16 + a_lr;
            uint32_t off = (uint32_t)row * 128 + (((uint32_t)(kb + a_cb)) ^ ((row & 7) << 4));
            ldm4(ah[mf], base + off);
        }
#pragma unroll
        for (int np = 0; np < 2; np++) {
            int row = n0 + np * 16 + b_lr;
            uint32_t off = (uint32_t)row * 128 + (((uint32_t)(kb + b_cb)) ^ ((row & 7) << 4));
            uint32_t t[4];
            ldm4(t, base + 16384 + off);
            bh[np * 2][0] = t[0]; bh[np * 2][1] = t[1];
            bh[np * 2 + 1][0] = t[2]; bh[np * 2 + 1][1] = t[3];
        }
#pragma unroll
        for (int mf = 0; mf < 2; mf++)
#pragma unroll
            for (int nf = 0; nf < 4; nf++) mma16816(F.acc[mf][nf], ah[mf], bh[nf]);
    }
}

// ================= GCN GEMM: out = A @ gwT^T  (N=128, K=128, 2 chunks) =================
// BATCH: A = xh (all t), out = g_xw0.  else: A = h0[a], out = g_xw1[b]
template<bool BATCH>
__global__ __launch_bounds__(512) void k_gcn(int a, int b) {
    extern __shared__ char smem[];
    uint32_t sb = smem_u32(smem);
    int tid = threadIdx.x, wid = tid >> 5, lane = tid & 31;
    int bm = blockIdx.x * 128;
    const __half* A = BATCH ? g_xh : g_h0[a];
    const __half* B = g_gwT[BATCH ? 0 : 1];
    __half* out = BATCH ? g_xw0 : g_xw1[b];

    auto load_chunk = [&](int c) {
        uint32_t bo = sb + (uint32_t)(c & 1) * BUFSZ;
        int cofs = c * 64;
        for (int i = tid; i < 1024; i += 512) {
            int r = i >> 3, j = i & 7;
            uint32_t so = swz128((uint32_t)r * 128 + j * 16);
            cp16(bo + so,         A + (size_t)(bm + r) * FIN + cofs + j * 8);
            cp16(bo + 16384 + so, B + (size_t)r * HH + cofs + j * 8);
        }
        asm volatile("cp.async.commit_group;" ::: "memory");
    };

    Frag F;
#pragma unroll
    for (int a2 = 0; a2 < 2; a2++)
#pragma unroll
        for (int b2 = 0; b2 < 4; b2++)
#pragma unroll
            for (int r = 0; r < 4; r++) F.acc[a2][b2][r] = 0.0f;

    int m0 = (wid & 3) * 32, n0 = (wid >> 2) * 32;
    load_chunk(0);
    load_chunk(1);
#pragma unroll
    for (int c = 0; c < 2; c++) {
        if (c + 1 < 2) asm volatile("cp.async.wait_group 1;" ::: "memory");
        else           asm volatile("cp.async.wait_group 0;" ::: "memory");
        __syncthreads();
        mma_chunk(sb + (uint32_t)(c & 1) * BUFSZ, m0, n0, lane, F);
        __syncthreads();
    }

    int tq = lane >> 2, tr = (lane & 3) * 2;
#pragma unroll
    for (int mf = 0; mf < 2; mf++)
#pragma unroll
        for (int nf = 0; nf < 4; nf++) {
            int row = bm + m0 + mf * 16 + tq;
            int col = n0 + nf * 8 + tr;
            *(__half2*)(out + (size_t)row * HH + col) =
                __floats2half2_rn(F.acc[mf][nf][0], F.acc[mf][nf][1]);
            *(__half2*)(out + (size_t)(row + 8) * HH + col) =
                __floats2half2_rn(F.acc[mf][nf][2], F.acc[mf][nf][3]);
        }
}

// ================= gate GEMM + fused LSTM cell (K=384, 6 chunks, 3-stage) =================
// L==0: A = [x[t] | g0[t] | h0[i0]], writes h0[i1], c0.
// L==1: A = [h0[i0] | g1[i1] | h1[i1^1]], writes h1[i1], c1, hout.   (i1 = t&1)
template<int L>
__global__ __launch_bounds__(512) void k_gate(int t, int i0, int i1) {
    extern __shared__ char smem[];
    uint32_t sb = smem_u32(smem);
    int tid = threadIdx.x, wid = tid >> 5, lane = tid & 31;
    int bm = blockIdx.x * 128, bn = blockIdx.y * 128;
    const __half* B = g_Wt[L];

    auto load_chunk = [&](int c) {
        uint32_t bo = sb + (uint32_t)(c % 3) * BUFSZ;
        const __half* A;
        int half_ = c >> 1;
        if (L == 0) {
            A = (half_ == 0) ? g_xh + (size_t)t * NP * FIN
              : (half_ == 1) ? g_g0 + (size_t)t * NP * HH : g_h0[i0];
        } else {
            A = (half_ == 0) ? g_h0[i0] : (half_ == 1) ? g_g1[i1] : g_h1[i1 ^ 1];
        }
        int cofs = (c & 1) * 64;
        int bk = c * 64;
        for (int i = tid; i < 1024; i += 512) {
            int r = i >> 3, j = i & 7;
            uint32_t so = swz128((uint32_t)r * 128 + j * 16);
            cp16(bo + so,         A + (size_t)(bm + r) * 128 + cofs + j * 8);
            cp16(bo + 16384 + so, B + (size_t)(bn + r) * GI + bk + j * 8);
        }
        asm volatile("cp.async.commit_group;" ::: "memory");
    };

    Frag F;
#pragma unroll
    for (int a = 0; a < 2; a++)
#pragma unroll
        for (int b = 0; b < 4; b++)
#pragma unroll
            for (int r = 0; r < 4; r++) F.acc[a][b][r] = 0.0f;

    int m0 = (wid & 3) * 32, n0 = (wid >> 2) * 32;
    load_chunk(0);
    load_chunk(1);
#pragma unroll
    for (int c = 0; c < 6; c++) {
        if (c + 2 < 6) { load_chunk(c + 2); asm volatile("cp.async.wait_group 2;" ::: "memory"); }
        else if (c + 1 < 6) asm volatile("cp.async.wait_group 1;" ::: "memory");
        else                asm volatile("cp.async.wait_group 0;" ::: "memory");
        __syncthreads();
        mma_chunk(sb + (uint32_t)(c % 3) * BUFSZ, m0, n0, lane, F);
        __syncthreads();
    }

    // fused LSTM pointwise epilogue (gate-interleaved packing: nf == gate)
    int tq = lane >> 2, tr = (lane & 3) * 2;
    int colbase = bn + n0;
    int fb = (colbase >> 5) * 8;
    const float* bias = g_b4[L];
#pragma unroll
    for (int mf = 0; mf < 2; mf++) {
#pragma unroll
        for (int h = 0; h < 2; h++) {
            int row = bm + m0 + mf * 16 + tq + h * 8;
#pragma unroll
            for (int e = 0; e < 2; e++) {
                int col0 = colbase + tr + e;
                float p0 = F.acc[mf][0][2 * h + e] + bias[col0];
                float p1 = F.acc[mf][1][2 * h + e] + bias[col0 + 8];
                float p2 = F.acc[mf][2][2 * h + e] + bias[col0 + 16];
                float p3 = F.acc[mf][3][2 * h + e] + bias[col0 + 24];
                float ft = sigmoidf_(p0), it = sigmoidf_(p1);
                float ot = sigmoidf_(p2), ct = tanhf(p3);
                size_t off = (size_t)row * 128 + fb + tr + e;
                float cn = ft * g_c[L][off] + it * ct;
                g_c[L][off] = cn;
                float hn = ot * tanhf(cn);
                if (L == 0) { g_h0[i1][off] = __float2half(hn); }
                else        { g_h1[i1][off] = __float2half(hn); g_hout[off] = hn; }
            }
        }
    }
}

// ---------------- GCN aggregation + sigmoid -> fp16 (fp16 xw gather) ----------------
// upfront: up=1, grid (NN, TT), t = blockIdx.y; in-loop: up=0, grid (NN), parity q
__global__ void k_aggregate(const float* __restrict__ gb, int up, int q) {
    int t = up ? blockIdx.y : 0;
    const __half* xw = up ? g_xw0 + (size_t)t * NP * HH : g_xw1[q];
    __half* og = up ? g_g0 + (size_t)t * NP * HH : g_g1[q];
    int n = blockIdx.x;
    int f = threadIdx.x;
    float disn = g_dis[n];
    float acc = disn * disn * __half2float(xw[(size_t)n * 128 + f]);
    int e2 = g_ptr[n + 1];
    int p = g_ptr[n];
    for (; p + 4 <= e2; p += 4) {
        int  s0 = g_src[p], s1 = g_src[p + 1], s2 = g_src[p + 2], s3 = g_src[p + 3];
        float w0 = g_wn[p], w1 = g_wn[p + 1], w2 = g_wn[p + 2], w3 = g_wn[p + 3];
        acc += w0 * __half2float(xw[(size_t)s0 * 128 + f]);
        acc += w1 * __half2float(xw[(size_t)s1 * 128 + f]);
        acc += w2 * __half2float(xw[(size_t)s2 * 128 + f]);
        acc += w3 * __half2float(xw[(size_t)s3 * 128 + f]);
    }
    for (; p < e2; p++) acc += g_wn[p] * __half2float(xw[(size_t)g_src[p] * 128 + f]);
    acc += gb[f];
    og[(size_t)n * 128 + f] = __float2half(sigmoidf_(acc));
}

// ---------------- output projection ----------------
__global__ void k_out(const float* __restrict__ ow, const float* __restrict__ ob,
                      float* __restrict__ out) {
    __shared__ float hs[4][128];
    int r0 = blockIdx.x * 4;
    int tid = threadIdx.x;
    for (int idx = tid; idx < 512; idx += 256) {
        int rr = idx >> 7, kk = idx & 127;
        int n = r0 + rr;
        hs[rr][kk] = (n < NN) ? g_hout[(size_t)n * 128 + kk] : 0.0f;
    }
    __syncthreads();
    int rr = tid >> 6, j = tid & 63;
    float acc = ob[j];
#pragma unroll 8
    for (int k = 0; k < 128; k++) acc += hs[rr][k] * ow[k * 64 + j];
    int n = r0 + rr;
    if (n < NN) out[(size_t)n * 64 + j] = acc;
}

// ---------------- launch (round-12 topology: serial prep, 2 side streams) ----------------
extern "C" void kernel_launch(void* const* d_in, const int* in_sizes, int n_in,
                              void* d_out, int out_size) {
    const float* x  = (const float*)d_in[0];
    const float* ea = (const float*)d_in[1];
    const int*   ei = (const int*)  d_in[2];
    const float* gw0 = (const float*)d_in[3];
    const float* gb0 = (const float*)d_in[4];
    const float* wf0 = (const float*)d_in[5];
    const float* bf0 = (const float*)d_in[6];
    const float* wi0 = (const float*)d_in[7];
    const float* bi0 = (const float*)d_in[8];
    const float* wo0 = (const float*)d_in[9];
    const float* bo0 = (const float*)d_in[10];
    const float* wc0 = (const float*)d_in[11];
    const float* bc0 = (const float*)d_in[12];
    const float* gw1 = (const float*)d_in[13];
    const float* gb1 = (const float*)d_in[14];
    const float* wf1 = (const float*)d_in[15];
    const float* bf1 = (const float*)d_in[16];
    const float* wi1 = (const float*)d_in[17];
    const float* bi1 = (const float*)d_in[18];
    const float* wo1 = (const float*)d_in[19];
    const float* bo1 = (const float*)d_in[20];
    const float* wc1 = (const float*)d_in[21];
    const float* bc1 = (const float*)d_in[22];
    const float* ow  = (const float*)d_in[23];
    const float* ob  = (const float*)d_in[24];
    float* out = (float*)d_out;

    static cudaStream_t sB = nullptr, sC = nullptr;
    static cudaEvent_t eA[TT], eB[TT], eC[TT], eEndB, eEndC;
    static bool inited = false;
    if (!inited) {
        cudaStreamCreateWithFlags(&sB, cudaStreamNonBlocking);
        cudaStreamCreateWithFlags(&sC, cudaStreamNonBlocking);
        for (int t = 0; t < TT; t++) {
            cudaEventCreateWithFlags(&eA[t], cudaEventDisableTiming);
            cudaEventCreateWithFlags(&eB[t], cudaEventDisableTiming);
            cudaEventCreateWithFlags(&eC[t], cudaEventDisableTiming);
        }
        cudaEventCreateWithFlags(&eEndB, cudaEventDisableTiming);
        cudaEventCreateWithFlags(&eEndC, cudaEventDisableTiming);
        cudaFuncSetAttribute(k_gate<0>, cudaFuncAttributeMaxDynamicSharedMemorySize, GATE_SMEM);
        cudaFuncSetAttribute(k_gate<1>, cudaFuncAttributeMaxDynamicSharedMemorySize, GATE_SMEM);
        cudaFuncSetAttribute(k_gcn<true>,  cudaFuncAttributeMaxDynamicSharedMemorySize, GCN_SMEM);
        cudaFuncSetAttribute(k_gcn<false>, cudaFuncAttributeMaxDynamicSharedMemorySize, GCN_SMEM);
        inited = true;
    }

    // ---- prep (default stream, serial) ----
    k_init_nodes<<<(NN + 255) / 256, 256>>>();
    k_edge_deg<<<EE / 256, 256>>>(ea, ei);
    k_node_prep<<<(NN + 255) / 256, 256>>>();
    k_scan<<<1, 1024>>>();
    k_edge_fill<<<EE / 256, 256>>>(ea, ei);

    k_transpose<<<(NN * FIN + 255) / 256, 256>>>(x);
    {
        int tot = (2 * TT + 2) * (NP - NN) * HH;
        k_zero_pads<<<(tot + 255) / 256, 256>>>();
    }
    k_zero_state<<<((long)NP * HH + 255) / 256, 256>>>();

    k_buildW<<<(G4 * GI + 255) / 256, 256>>>(wf0, wi0, wo0, wc0, bf0, bi0, bo0, bc0, 0);
    k_buildW<<<(G4 * GI + 255) / 256, 256>>>(wf1, wi1, wo1, wc1, bf1, bi1, bo1, bc1, 1);
    k_buildGW<<<(HH * HH + 255) / 256, 256>>>(gw0, 0);
    k_buildGW<<<(HH * HH + 255) / 256, 256>>>(gw1, 1);

    // ---- upfront layer-0 x-dependent work ----
    k_gcn<true><<<MT / 128, 512, GCN_SMEM>>>(0, 0);                // xw0 all t
    k_aggregate<<<dim3(NN, TT), 128>>>(gb0, 1, 0);                 // g0 all t (one launch)

    // ---- overlapped time loop ----
    // stream0: gate0 chain; sB: gcn+agg; sC: gate1 chain
    for (int t = 0; t < TT; t++) {
        int q = t & 1;
        int h0w = t % 3;             // gate0 writes h0[h0w]
        int h0r = (t + 2) % 3;       // gate0 reads h0[(t-1)%3]; buffer 2 zeroed for t=0
        if (t >= 3) cudaStreamWaitEvent(0, eC[t - 3], 0);   // h0[h0w] prior readers done
        k_gate<0><<<dim3(NP / 128, 4), 512, GATE_SMEM, 0>>>(t, h0r, h0w);
        cudaEventRecord(eA[t], 0);

        if (t >= 2) cudaStreamWaitEvent(sB, eC[t - 2], 0);  // g1[q]/xw1[q] prior readers done
        cudaStreamWaitEvent(sB, eA[t], 0);
        k_gcn<false><<<NP / 128, 512, GCN_SMEM, sB>>>(h0w, q);
        k_aggregate<<<NN, 128, 0, sB>>>(gb1, 0, q);
        cudaEventRecord(eB[t], sB);

        cudaStreamWaitEvent(sC, eB[t], 0);
        k_gate<1><<<dim3(NP / 128, 4), 512, GATE_SMEM, sC>>>(t, h0w, q);
        cudaEventRecord(eC[t], sC);
    }

    k_out<<<(NN + 3) / 4, 256, 0, sC>>>(ow, ob, out);
    cudaEventRecord(eEndC, sC);
    cudaEventRecord(eEndB, sB);
    cudaStreamWaitEvent(0, eEndB, 0);
    cudaStreamWaitEvent(0, eEndC, 0);
}

// round 15
// speedup vs baseline: 1.2584x; 1.2584x over previous
#include <cuda_runtime.h>
#include <cuda_fp16.h>
#include <math.h>
#include <stdint.h>

#define NN   20000
#define NP   20096      // 157 * 128
#define EE   640000
#define FIN  128
#define HH   128
#define TT   12
#define NOUT 64
#define GI   384
#define G4   512
#define MT   (TT * NP)  // 241152 batched rows

// ---------------- scratch ----------------
__device__ __half g_xh[(size_t)MT * FIN];        // x transposed+rounded, all t
__device__ __half g_g0[(size_t)MT * HH];         // upfront g0 per t
__device__ float  g_xw0[(size_t)MT * HH];        // upfront batched GCN out (fp32)
__device__ __half g_h0[3][(size_t)NP * HH];      // h0 triple buffer (mod 3)
__device__ __half g_h1[2][(size_t)NP * HH];      // h1 parity
__device__ float  g_c[2][(size_t)NP * HH];
__device__ float  g_hout[(size_t)NP * HH];
__device__ float  g_xw1[2][(size_t)NP * HH];     // in-loop gcn out, parity (fp32)
__device__ __half g_g1[2][(size_t)NP * HH];      // in-loop g, parity
__device__ __half g_Wt[2][G4 * GI];      // [pc=512][k=384] gate-interleaved, fp16
__device__ __half g_gwT[2][HH * HH];     // fp16
__device__ float  g_b4[2][G4];           // packed by pc
__device__ float g_deg[NN];
__device__ float g_dis[NN];
__device__ int   g_cnt[NN];
__device__ int   g_cur[NN];
__device__ int   g_ptr[NN + 1];
__device__ int   g_src[EE];
__device__ float g_wn[EE];

__device__ __forceinline__ float sigmoidf_(float x) { return 1.0f / (1.0f + expf(-x)); }
__device__ __forceinline__ uint32_t smem_u32(const void* p) {
    return (uint32_t)__cvta_generic_to_shared(p);
}
__device__ __forceinline__ uint32_t swz128(uint32_t o) { return o ^ ((o >> 3) & 0x70); }
__device__ __forceinline__ void cp16(uint32_t dst, const void* src) {
    asm volatile("cp.async.cg.shared.global [%0], [%1], 16;" :: "r"(dst), "l"(src));
}
__device__ __forceinline__ void ldm4(uint32_t* r, uint32_t addr) {
    asm volatile("ldmatrix.sync.aligned.m8n8.x4.shared.b16 {%0,%1,%2,%3}, [%4];"
                 : "=r"(r[0]), "=r"(r[1]), "=r"(r[2]), "=r"(r[3]) : "r"(addr));
}
__device__ __forceinline__ void mma16816(float* c, const uint32_t* a, const uint32_t* b) {
    asm volatile("mma.sync.aligned.m16n8k16.row.col.f32.f16.f16.f32 "
                 "{%0,%1,%2,%3}, {%4,%5,%6,%7}, {%8,%9}, {%0,%1,%2,%3};"
                 : "+f"(c[0]), "+f"(c[1]), "+f"(c[2]), "+f"(c[3])
                 : "r"(a[0]), "r"(a[1]), "r"(a[2]), "r"(a[3]), "r"(b[0]), "r"(b[1]));
}

// ---------------- graph preprocessing ----------------
__global__ void k_init_nodes() {
    int i = blockIdx.x * blockDim.x + threadIdx.x;
    if (i < NN) { g_deg[i] = 1.0f; g_cnt[i] = 0; }
}
__global__ void k_edge_deg(const float* __restrict__ ea, const int* __restrict__ ei) {
    int e = blockIdx.x * blockDim.x + threadIdx.x;
    if (e < EE) {
        int c = ei[EE + e];
        atomicAdd(&g_deg[c], ea[4 * e + 3]);
        atomicAdd(&g_cnt[c], 1);
    }
}
__global__ void k_node_prep() {
    int i = blockIdx.x * blockDim.x + threadIdx.x;
    if (i < NN) { g_dis[i] = rsqrtf(g_deg[i]); g_cur[i] = 0; }
}
__global__ void k_scan() {
    __shared__ int sh[2][1024];
    __shared__ int carry;
    int tid = threadIdx.x;
    if (tid == 0) carry = 0;
    __syncthreads();
    for (int base = 0; base < NN; base += 1024) {
        int v = (base + tid < NN) ? g_cnt[base + tid] : 0;
        int buf = 0;
        sh[0][tid] = v;
        __syncthreads();
        for (int off = 1; off < 1024; off <<= 1) {
            int val = sh[buf][tid];
            if (tid >= off) val += sh[buf][tid - off];
            sh[buf ^ 1][tid] = val;
            buf ^= 1;
            __syncthreads();
        }
        int incl = sh[buf][tid];
        int c0 = carry;
        if (base + tid < NN) g_ptr[base + tid] = c0 + incl - v;
        __syncthreads();
        if (tid == 1023) carry = c0 + sh[buf][1023];
        __syncthreads();
    }
    if (tid == 0) g_ptr[NN] = carry;
}
__global__ void k_edge_fill(const float* __restrict__ ea, const int* __restrict__ ei) {
    int e = blockIdx.x * blockDim.x + threadIdx.x;
    if (e < EE) {
        int r = ei[e];
        int c = ei[EE + e];
        float w = ea[4 * e + 3];
        int pos = g_ptr[c] + atomicAdd(&g_cur[c], 1);
        g_src[pos] = r;
        g_wn[pos]  = g_dis[r] * w * g_dis[c];
    }
}

// ---------------- input transpose (fp32 -> fp16) ----------------
__global__ void k_transpose(const float* __restrict__ x) {
    long nf = (long)blockIdx.x * blockDim.x + threadIdx.x;
    if (nf >= (long)NN * FIN) return;
    float v[TT];
#pragma unroll
    for (int t = 0; t < TT; t++) v[t] = x[nf * TT + t];
#pragma unroll
    for (int t = 0; t < TT; t++)
        g_xh[(long)t * NP * FIN + nf] = __float2half(v[t]);
}

// slices: s<TT: xh[t] pads; s<2TT: g0[t] pads; s=2TT,2TT+1: g1[parity] pads
__global__ void k_zero_pads() {
    const int padN = (NP - NN) * HH;   // 12288
    int i = blockIdx.x * blockDim.x + threadIdx.x;
    int s = i / padN, r = i % padN;
    if (s >= 2 * TT + 2) return;
    __half z = __float2half(0.0f);
    if (s < TT) {
        g_xh[(long)s * NP * FIN + (long)NN * FIN + r] = z;
    } else if (s < 2 * TT) {
        g_g0[(long)(s - TT) * NP * HH + (long)NN * HH + r] = z;
    } else {
        g_g1[s - 2 * TT][(long)NN * HH + r] = z;
    }
}

__global__ void k_zero_state() {
    long i = (long)blockIdx.x * blockDim.x + threadIdx.x;
    if (i < (long)NP * HH) {
        __half z = __float2half(0.0f);
        g_c[0][i] = 0.0f; g_c[1][i] = 0.0f;
#pragma unroll
        for (int p = 0; p < 3; p++) g_h0[p][i] = z;
#pragma unroll
        for (int p = 0; p < 2; p++) g_h1[p][i] = z;
    }
}

// ---------------- pack gate weights: pc = ((f>>3)<<5)|(g<<3)|(f&7) ----------------
__global__ void k_buildW(const float* __restrict__ wf, const float* __restrict__ wi,
                         const float* __restrict__ wo, const float* __restrict__ wc,
                         const float* __restrict__ bf, const float* __restrict__ bi,
                         const float* __restrict__ bo, const float* __restrict__ bc,
                         int layer) {
    int idx = blockIdx.x * blockDim.x + threadIdx.x;
    if (idx >= G4 * GI) return;
    int pc = idx / GI, k = idx % GI;
    int f = ((pc >> 5) << 3) | (pc & 7);
    int g = (pc >> 3) & 3;
    const float* w = (g == 0) ? wf : (g == 1) ? wi : (g == 2) ? wo : wc;
    g_Wt[layer][idx] = __float2half(w[k * 128 + f]);
    if (k == 0) {
        const float* b = (g == 0) ? bf : (g == 1) ? bi : (g == 2) ? bo : bc;
        g_b4[layer][pc] = b[f];
    }
}

__global__ void k_buildGW(const float* __restrict__ gw, int layer) {
    int idx = blockIdx.x * blockDim.x + threadIdx.x;
    if (idx >= HH * HH) return;
    int n = idx >> 7, k = idx & 127;
    g_gwT[layer][idx] = __float2half(gw[k * 128 + n]);
}

// ================= shared MMA mainloop =================
// 512 threads, 16 warps (4M x 4N of 32x32), tile 128x128, K chunks of 64.
// per-buffer layout: A 16K | B 16K (SW128 swizzled), single fp16 pass
#define BUFSZ 32768u
#define GATE_SMEM (3 * 32768)   // 3-stage
#define GCN_SMEM  (2 * 32768)   // 2-stage

struct Frag { float acc[2][4][4]; };

__device__ __forceinline__ void mma_chunk(uint32_t base, int m0, int n0, int lane, Frag& F) {
    int a_lr = ((lane >> 3) & 1) * 8 + (lane & 7);
    int a_cb = (lane >> 4) * 16;
    int b_lr = (lane >> 4) * 8 + (lane & 7);
    int b_cb = ((lane >> 3) & 1) * 16;
#pragma unroll
    for (int ks = 0; ks < 4; ks++) {
        int kb = ks * 32;
        uint32_t ah[2][4], bh[4][2];
#pragma unroll
        for (int mf = 0; mf < 2; mf++) {
            int row = m0 + mf * 16 + a_lr;
            uint32_t off = (uint32_t)row * 128 + (((uint32_t)(kb + a_cb)) ^ ((row & 7) << 4));
            ldm4(ah[mf], base + off);
        }
#pragma unroll
        for (int np = 0; np < 2; np++) {
            int row = n0 + np * 16 + b_lr;
            uint32_t off = (uint32_t)row * 128 + (((uint32_t)(kb + b_cb)) ^ ((row & 7) << 4));
            uint32_t t[4];
            ldm4(t, base + 16384 + off);
            bh[np * 2][0] = t[0]; bh[np * 2][1] = t[1];
            bh[np * 2 + 1][0] = t[2]; bh[np * 2 + 1][1] = t[3];
        }
#pragma unroll
        for (int mf = 0; mf < 2; mf++)
#pragma unroll
            for (int nf = 0; nf < 4; nf++) mma16816(F.acc[mf][nf], ah[mf], bh[nf]);
    }
}

// ================= GCN GEMM: out = A @ gwT^T  (N=128, K=128, 2 chunks) =================
// BATCH: A = xh (all t), out = g_xw0.  else: A = h0[a], out = g_xw1[b]
template<bool BATCH>
__global__ __launch_bounds__(512) void k_gcn(int a, int b) {
    extern __shared__ char smem[];
    uint32_t sb = smem_u32(smem);
    int tid = threadIdx.x, wid = tid >> 5, lane = tid & 31;
    int bm = blockIdx.x * 128;
    const __half* A = BATCH ? g_xh : g_h0[a];
    const __half* B = g_gwT[BATCH ? 0 : 1];
    float* out = BATCH ? g_xw0 : g_xw1[b];

    auto load_chunk = [&](int c) {
        uint32_t bo = sb + (uint32_t)(c & 1) * BUFSZ;
        int cofs = c * 64;
        for (int i = tid; i < 1024; i += 512) {
            int r = i >> 3, j = i & 7;
            uint32_t so = swz128((uint32_t)r * 128 + j * 16);
            cp16(bo + so,         A + (size_t)(bm + r) * FIN + cofs + j * 8);
            cp16(bo + 16384 + so, B + (size_t)r * HH + cofs + j * 8);
        }
        asm volatile("cp.async.commit_group;" ::: "memory");
    };

    Frag F;
#pragma unroll
    for (int a2 = 0; a2 < 2; a2++)
#pragma unroll
        for (int b2 = 0; b2 < 4; b2++)
#pragma unroll
            for (int r = 0; r < 4; r++) F.acc[a2][b2][r] = 0.0f;

    int m0 = (wid & 3) * 32, n0 = (wid >> 2) * 32;
    load_chunk(0);
    load_chunk(1);
#pragma unroll
    for (int c = 0; c < 2; c++) {
        if (c + 1 < 2) asm volatile("cp.async.wait_group 1;" ::: "memory");
        else           asm volatile("cp.async.wait_group 0;" ::: "memory");
        __syncthreads();
        mma_chunk(sb + (uint32_t)(c & 1) * BUFSZ, m0, n0, lane, F);
        __syncthreads();
    }

    int tq = lane >> 2, tr = (lane & 3) * 2;
#pragma unroll
    for (int mf = 0; mf < 2; mf++)
#pragma unroll
        for (int nf = 0; nf < 4; nf++) {
            int row = bm + m0 + mf * 16 + tq;
            int col = n0 + nf * 8 + tr;
            *(float2*)(out + (size_t)row * HH + col) = make_float2(F.acc[mf][nf][0], F.acc[mf][nf][1]);
            *(float2*)(out + (size_t)(row + 8) * HH + col) = make_float2(F.acc[mf][nf][2], F.acc[mf][nf][3]);
        }
}

// ================= gate GEMM + fused LSTM cell (K=384, 6 chunks, 3-stage) =================
// L==0: A = [x[t] | g0[t] | h0[i0]], writes h0[i1], c0.
// L==1: A = [h0[i0] | g1[i1] | h1[i1^1]], writes h1[i1], c1, hout.   (i1 = t&1)
template<int L>
__global__ __launch_bounds__(512) void k_gate(int t, int i0, int i1) {
    extern __shared__ char smem[];
    uint32_t sb = smem_u32(smem);
    int tid = threadIdx.x, wid = tid >> 5, lane = tid & 31;
    int bm = blockIdx.x * 128, bn = blockIdx.y * 128;
    const __half* B = g_Wt[L];

    auto load_chunk = [&](int c) {
        uint32_t bo = sb + (uint32_t)(c % 3) * BUFSZ;
        const __half* A;
        int half_ = c >> 1;
        if (L == 0) {
            A = (half_ == 0) ? g_xh + (size_t)t * NP * FIN
              : (half_ == 1) ? g_g0 + (size_t)t * NP * HH : g_h0[i0];
        } else {
            A = (half_ == 0) ? g_h0[i0] : (half_ == 1) ? g_g1[i1] : g_h1[i1 ^ 1];
        }
        int cofs = (c & 1) * 64;
        int bk = c * 64;
        for (int i = tid; i < 1024; i += 512) {
            int r = i >> 3, j = i & 7;
            uint32_t so = swz128((uint32_t)r * 128 + j * 16);
            cp16(bo + so,         A + (size_t)(bm + r) * 128 + cofs + j * 8);
            cp16(bo + 16384 + so, B + (size_t)(bn + r) * GI + bk + j * 8);
        }
        asm volatile("cp.async.commit_group;" ::: "memory");
    };

    Frag F;
#pragma unroll
    for (int a = 0; a < 2; a++)
#pragma unroll
        for (int b = 0; b < 4; b++)
#pragma unroll
            for (int r = 0; r < 4; r++) F.acc[a][b][r] = 0.0f;

    int m0 = (wid & 3) * 32, n0 = (wid >> 2) * 32;
    load_chunk(0);
    load_chunk(1);
#pragma unroll
    for (int c = 0; c < 6; c++) {
        if (c + 2 < 6) { load_chunk(c + 2); asm volatile("cp.async.wait_group 2;" ::: "memory"); }
        else if (c + 1 < 6) asm volatile("cp.async.wait_group 1;" ::: "memory");
        else                asm volatile("cp.async.wait_group 0;" ::: "memory");
        __syncthreads();
        mma_chunk(sb + (uint32_t)(c % 3) * BUFSZ, m0, n0, lane, F);
        __syncthreads();
    }

    // fused LSTM pointwise epilogue (gate-interleaved packing: nf == gate)
    int tq = lane >> 2, tr = (lane & 3) * 2;
    int colbase = bn + n0;
    int fb = (colbase >> 5) * 8;
    const float* bias = g_b4[L];
#pragma unroll
    for (int mf = 0; mf < 2; mf++) {
#pragma unroll
        for (int h = 0; h < 2; h++) {
            int row = bm + m0 + mf * 16 + tq + h * 8;
#pragma unroll
            for (int e = 0; e < 2; e++) {
                int col0 = colbase + tr + e;
                float p0 = F.acc[mf][0][2 * h + e] + bias[col0];
                float p1 = F.acc[mf][1][2 * h + e] + bias[col0 + 8];
                float p2 = F.acc[mf][2][2 * h + e] + bias[col0 + 16];
                float p3 = F.acc[mf][3][2 * h + e] + bias[col0 + 24];
                float ft = sigmoidf_(p0), it = sigmoidf_(p1);
                float ot = sigmoidf_(p2), ct = tanhf(p3);
                size_t off = (size_t)row * 128 + fb + tr + e;
                float cn = ft * g_c[L][off] + it * ct;
                g_c[L][off] = cn;
                float hn = ot * tanhf(cn);
                if (L == 0) { g_h0[i1][off] = __float2half(hn); }
                else        { g_h1[i1][off] = __float2half(hn); g_hout[off] = hn; }
            }
        }
    }
}

// ---------------- GCN aggregation + sigmoid -> fp16 ----------------
// warp-per-node, float4 per lane (lane covers features lane*4..lane*4+3).
// upfront: up=1, grid (NN/4, TT), t = blockIdx.y; in-loop: up=0, grid (NN/4), parity q
__global__ __launch_bounds__(128) void k_aggregate(const float* __restrict__ gb, int up, int q) {
    int t = up ? blockIdx.y : 0;
    const float* xw = up ? g_xw0 + (size_t)t * NP * HH : g_xw1[q];
    __half* og = up ? g_g0 + (size_t)t * NP * HH : g_g1[q];
    int w = threadIdx.x >> 5, lane = threadIdx.x & 31;
    int n = blockIdx.x * 4 + w;
    int fc = lane * 4;

    float disn = g_dis[n];
    float s2 = disn * disn;
    float4 v = *(const float4*)(xw + (size_t)n * 128 + fc);
    float4 acc = make_float4(s2 * v.x, s2 * v.y, s2 * v.z, s2 * v.w);

    int p = g_ptr[n], e2 = g_ptr[n + 1];
    for (; p + 4 <= e2; p += 4) {
        int  s0 = g_src[p], s1 = g_src[p + 1], s2i = g_src[p + 2], s3 = g_src[p + 3];
        float w0 = g_wn[p], w1 = g_wn[p + 1], w2 = g_wn[p + 2], w3 = g_wn[p + 3];
        float4 v0 = *(const float4*)(xw + (size_t)s0 * 128 + fc);
        float4 v1 = *(const float4*)(xw + (size_t)s1 * 128 + fc);
        float4 v2 = *(const float4*)(xw + (size_t)s2i * 128 + fc);
        float4 v3 = *(const float4*)(xw + (size_t)s3 * 128 + fc);
        acc.x += w0 * v0.x + w1 * v1.x + w2 * v2.x + w3 * v3.x;
        acc.y += w0 * v0.y + w1 * v1.y + w2 * v2.y + w3 * v3.y;
        acc.z += w0 * v0.z + w1 * v1.z + w2 * v2.z + w3 * v3.z;
        acc.w += w0 * v0.w + w1 * v1.w + w2 * v2.w + w3 * v3.w;
    }
    for (; p < e2; p++) {
        float we = g_wn[p];
        float4 ve = *(const float4*)(xw + (size_t)g_src[p] * 128 + fc);
        acc.x += we * ve.x; acc.y += we * ve.y;
        acc.z += we * ve.z; acc.w += we * ve.w;
    }
    float4 b = *(const float4*)(gb + fc);
    __half2 o0 = __floats2half2_rn(sigmoidf_(acc.x + b.x), sigmoidf_(acc.y + b.y));
    __half2 o1 = __floats2half2_rn(sigmoidf_(acc.z + b.z), sigmoidf_(acc.w + b.w));
    __half2* dst = (__half2*)(og + (size_t)n * 128 + fc);
    dst[0] = o0;
    dst[1] = o1;
}

// ---------------- output projection ----------------
__global__ void k_out(const float* __restrict__ ow, const float* __restrict__ ob,
                      float* __restrict__ out) {
    __shared__ float hs[4][128];
    int r0 = blockIdx.x * 4;
    int tid = threadIdx.x;
    for (int idx = tid; idx < 512; idx += 256) {
        int rr = idx >> 7, kk = idx & 127;
        int n = r0 + rr;
        hs[rr][kk] = (n < NN) ? g_hout[(size_t)n * 128 + kk] : 0.0f;
    }
    __syncthreads();
    int rr = tid >> 6, j = tid & 63;
    float acc = ob[j];
#pragma unroll 8
    for (int k = 0; k < 128; k++) acc += hs[rr][k] * ow[k * 64 + j];
    int n = r0 + rr;
    if (n < NN) out[(size_t)n * 64 + j] = acc;
}

// ---------------- launch (round-12 topology: serial prep, 2 side streams) ----------------
extern "C" void kernel_launch(void* const* d_in, const int* in_sizes, int n_in,
                              void* d_out, int out_size) {
    const float* x  = (const float*)d_in[0];
    const float* ea = (const float*)d_in[1];
    const int*   ei = (const int*)  d_in[2];
    const float* gw0 = (const float*)d_in[3];
    const float* gb0 = (const float*)d_in[4];
    const float* wf0 = (const float*)d_in[5];
    const float* bf0 = (const float*)d_in[6];
    const float* wi0 = (const float*)d_in[7];
    const float* bi0 = (const float*)d_in[8];
    const float* wo0 = (const float*)d_in[9];
    const float* bo0 = (const float*)d_in[10];
    const float* wc0 = (const float*)d_in[11];
    const float* bc0 = (const float*)d_in[12];
    const float* gw1 = (const float*)d_in[13];
    const float* gb1 = (const float*)d_in[14];
    const float* wf1 = (const float*)d_in[15];
    const float* bf1 = (const float*)d_in[16];
    const float* wi1 = (const float*)d_in[17];
    const float* bi1 = (const float*)d_in[18];
    const float* wo1 = (const float*)d_in[19];
    const float* bo1 = (const float*)d_in[20];
    const float* wc1 = (const float*)d_in[21];
    const float* bc1 = (const float*)d_in[22];
    const float* ow  = (const float*)d_in[23];
    const float* ob  = (const float*)d_in[24];
    float* out = (float*)d_out;

    static cudaStream_t sB = nullptr, sC = nullptr;
    static cudaEvent_t eA[TT], eB[TT], eC[TT], eEndB, eEndC;
    static bool inited = false;
    if (!inited) {
        cudaStreamCreateWithFlags(&sB, cudaStreamNonBlocking);
        cudaStreamCreateWithFlags(&sC, cudaStreamNonBlocking);
        for (int t = 0; t < TT; t++) {
            cudaEventCreateWithFlags(&eA[t], cudaEventDisableTiming);
            cudaEventCreateWithFlags(&eB[t], cudaEventDisableTiming);
            cudaEventCreateWithFlags(&eC[t], cudaEventDisableTiming);
        }
        cudaEventCreateWithFlags(&eEndB, cudaEventDisableTiming);
        cudaEventCreateWithFlags(&eEndC, cudaEventDisableTiming);
        cudaFuncSetAttribute(k_gate<0>, cudaFuncAttributeMaxDynamicSharedMemorySize, GATE_SMEM);
        cudaFuncSetAttribute(k_gate<1>, cudaFuncAttributeMaxDynamicSharedMemorySize, GATE_SMEM);
        cudaFuncSetAttribute(k_gcn<true>,  cudaFuncAttributeMaxDynamicSharedMemorySize, GCN_SMEM);
        cudaFuncSetAttribute(k_gcn<false>, cudaFuncAttributeMaxDynamicSharedMemorySize, GCN_SMEM);
        inited = true;
    }

    // ---- prep (default stream, serial) ----
    k_init_nodes<<<(NN + 255) / 256, 256>>>();
    k_edge_deg<<<EE / 256, 256>>>(ea, ei);
    k_node_prep<<<(NN + 255) / 256, 256>>>();
    k_scan<<<1, 1024>>>();
    k_edge_fill<<<EE / 256, 256>>>(ea, ei);

    k_transpose<<<(NN * FIN + 255) / 256, 256>>>(x);
    {
        int tot = (2 * TT + 2) * (NP - NN) * HH;
        k_zero_pads<<<(tot + 255) / 256, 256>>>();
    }
    k_zero_state<<<((long)NP * HH + 255) / 256, 256>>>();

    k_buildW<<<(G4 * GI + 255) / 256, 256>>>(wf0, wi0, wo0, wc0, bf0, bi0, bo0, bc0, 0);
    k_buildW<<<(G4 * GI + 255) / 256, 256>>>(wf1, wi1, wo1, wc1, bf1, bi1, bo1, bc1, 1);
    k_buildGW<<<(HH * HH + 255) / 256, 256>>>(gw0, 0);
    k_buildGW<<<(HH * HH + 255) / 256, 256>>>(gw1, 1);

    // ---- upfront layer-0 x-dependent work ----
    k_gcn<true><<<MT / 128, 512, GCN_SMEM>>>(0, 0);                // xw0 all t
    k_aggregate<<<dim3(NN / 4, TT), 128>>>(gb0, 1, 0);             // g0 all t (one launch)

    // ---- overlapped time loop ----
    // stream0: gate0 chain; sB: gcn+agg; sC: gate1 chain
    for (int t = 0; t < TT; t++) {
        int q = t & 1;
        int h0w = t % 3;             // gate0 writes h0[h0w]
        int h0r = (t + 2) % 3;       // gate0 reads h0[(t-1)%3]; buffer 2 zeroed for t=0
        if (t >= 3) cudaStreamWaitEvent(0, eC[t - 3], 0);   // h0[h0w] prior readers done
        k_gate<0><<<dim3(NP / 128, 4), 512, GATE_SMEM, 0>>>(t, h0r, h0w);
        cudaEventRecord(eA[t], 0);

        if (t >= 2) cudaStreamWaitEvent(sB, eC[t - 2], 0);  // g1[q]/xw1[q] prior readers done
        cudaStreamWaitEvent(sB, eA[t], 0);
        k_gcn<false><<<NP / 128, 512, GCN_SMEM, sB>>>(h0w, q);
        k_aggregate<<<NN / 4, 128, 0, sB>>>(gb1, 0, q);
        cudaEventRecord(eB[t], sB);

        cudaStreamWaitEvent(sC, eB[t], 0);
        k_gate<1><<<dim3(NP / 128, 4), 512, GATE_SMEM, sC>>>(t, h0w, q);
        cudaEventRecord(eC[t], sC);
    }

    k_out<<<(NN + 3) / 4, 256, 0, sC>>>(ow, ob, out);
    cudaEventRecord(eEndC, sC);
    cudaEventRecord(eEndB, sB);
    cudaStreamWaitEvent(0, eEndB, 0);
    cudaStreamWaitEvent(0, eEndC, 0);
}

// round 16
// speedup vs baseline: 1.2747x; 1.0129x over previous
#include <cuda_runtime.h>
#include <cuda_fp16.h>
#include <math.h>
#include <stdint.h>

#define NN   20000
#define NP   20096      // 157 * 128
#define EE   640000
#define FIN  128
#define HH   128
#define TT   12
#define NOUT 64
#define GI   384
#define G4   512
#define MT   (TT * NP)  // 241152 batched rows

// ---------------- scratch ----------------
__device__ __half g_xh[(size_t)MT * FIN];        // x transposed+rounded, all t
__device__ __half g_g0[(size_t)MT * HH];         // upfront g0 per t
__device__ float  g_xw0[(size_t)MT * HH];        // upfront batched GCN out (fp32)
__device__ __half g_h0[3][(size_t)NP * HH];      // h0 triple buffer (mod 3)
__device__ __half g_h1[2][(size_t)NP * HH];      // h1 parity
__device__ float  g_c[2][(size_t)NP * HH];
__device__ float  g_hout[(size_t)NP * HH];
__device__ float  g_xw1[2][(size_t)NP * HH];     // in-loop gcn out, parity (fp32)
__device__ __half g_g1[2][(size_t)NP * HH];      // in-loop g, parity
__device__ __half g_Wt[2][G4 * GI];      // [pc=512][k=384] gate-interleaved, fp16
__device__ __half g_gwT[2][HH * HH];     // fp16
__device__ float  g_b4[2][G4];           // packed by pc
__device__ float g_deg[NN];
__device__ float g_dis[NN];
__device__ int   g_cnt[NN];
__device__ int   g_cur[NN];
__device__ int   g_ptr[NN + 1];
__device__ int   g_src[EE];
__device__ float g_wn[EE];

__device__ __forceinline__ float sigmoidf_(float x) { return 1.0f / (1.0f + expf(-x)); }
__device__ __forceinline__ uint32_t smem_u32(const void* p) {
    return (uint32_t)__cvta_generic_to_shared(p);
}
__device__ __forceinline__ uint32_t swz128(uint32_t o) { return o ^ ((o >> 3) & 0x70); }
__device__ __forceinline__ void cp16(uint32_t dst, const void* src) {
    asm volatile("cp.async.cg.shared.global [%0], [%1], 16;" :: "r"(dst), "l"(src));
}
__device__ __forceinline__ void ldm4(uint32_t* r, uint32_t addr) {
    asm volatile("ldmatrix.sync.aligned.m8n8.x4.shared.b16 {%0,%1,%2,%3}, [%4];"
                 : "=r"(r[0]), "=r"(r[1]), "=r"(r[2]), "=r"(r[3]) : "r"(addr));
}
__device__ __forceinline__ void mma16816(float* c, const uint32_t* a, const uint32_t* b) {
    asm volatile("mma.sync.aligned.m16n8k16.row.col.f32.f16.f16.f32 "
                 "{%0,%1,%2,%3}, {%4,%5,%6,%7}, {%8,%9}, {%0,%1,%2,%3};"
                 : "+f"(c[0]), "+f"(c[1]), "+f"(c[2]), "+f"(c[3])
                 : "r"(a[0]), "r"(a[1]), "r"(a[2]), "r"(a[3]), "r"(b[0]), "r"(b[1]));
}

// ---------------- graph preprocessing ----------------
__global__ void k_init_nodes() {
    int i = blockIdx.x * blockDim.x + threadIdx.x;
    if (i < NN) { g_deg[i] = 1.0f; g_cnt[i] = 0; }
}
__global__ void k_edge_deg(const float* __restrict__ ea, const int* __restrict__ ei) {
    int e = blockIdx.x * blockDim.x + threadIdx.x;
    if (e < EE) {
        int c = ei[EE + e];
        atomicAdd(&g_deg[c], ea[4 * e + 3]);
        atomicAdd(&g_cnt[c], 1);
    }
}
__global__ void k_node_prep() {
    int i = blockIdx.x * blockDim.x + threadIdx.x;
    if (i < NN) { g_dis[i] = rsqrtf(g_deg[i]); g_cur[i] = 0; }
}
__global__ void k_scan() {
    __shared__ int sh[2][1024];
    __shared__ int carry;
    int tid = threadIdx.x;
    if (tid == 0) carry = 0;
    __syncthreads();
    for (int base = 0; base < NN; base += 1024) {
        int v = (base + tid < NN) ? g_cnt[base + tid] : 0;
        int buf = 0;
        sh[0][tid] = v;
        __syncthreads();
        for (int off = 1; off < 1024; off <<= 1) {
            int val = sh[buf][tid];
            if (tid >= off) val += sh[buf][tid - off];
            sh[buf ^ 1][tid] = val;
            buf ^= 1;
            __syncthreads();
        }
        int incl = sh[buf][tid];
        int c0 = carry;
        if (base + tid < NN) g_ptr[base + tid] = c0 + incl - v;
        __syncthreads();
        if (tid == 1023) carry = c0 + sh[buf][1023];
        __syncthreads();
    }
    if (tid == 0) g_ptr[NN] = carry;
}
__global__ void k_edge_fill(const float* __restrict__ ea, const int* __restrict__ ei) {
    int e = blockIdx.x * blockDim.x + threadIdx.x;
    if (e < EE) {
        int r = ei[e];
        int c = ei[EE + e];
        float w = ea[4 * e + 3];
        int pos = g_ptr[c] + atomicAdd(&g_cur[c], 1);
        g_src[pos] = r;
        g_wn[pos]  = g_dis[r] * w * g_dis[c];
    }
}

// ---------------- input transpose (fp32 -> fp16) ----------------
__global__ void k_transpose(const float* __restrict__ x) {
    long nf = (long)blockIdx.x * blockDim.x + threadIdx.x;
    if (nf >= (long)NN * FIN) return;
    float v[TT];
#pragma unroll
    for (int t = 0; t < TT; t++) v[t] = x[nf * TT + t];
#pragma unroll
    for (int t = 0; t < TT; t++)
        g_xh[(long)t * NP * FIN + nf] = __float2half(v[t]);
}

// slices: s<TT: xh[t] pads; s<2TT: g0[t] pads; s=2TT,2TT+1: g1[parity] pads
__global__ void k_zero_pads() {
    const int padN = (NP - NN) * HH;   // 12288
    int i = blockIdx.x * blockDim.x + threadIdx.x;
    int s = i / padN, r = i % padN;
    if (s >= 2 * TT + 2) return;
    __half z = __float2half(0.0f);
    if (s < TT) {
        g_xh[(long)s * NP * FIN + (long)NN * FIN + r] = z;
    } else if (s < 2 * TT) {
        g_g0[(long)(s - TT) * NP * HH + (long)NN * HH + r] = z;
    } else {
        g_g1[s - 2 * TT][(long)NN * HH + r] = z;
    }
}

__global__ void k_zero_state() {
    long i = (long)blockIdx.x * blockDim.x + threadIdx.x;
    if (i < (long)NP * HH) {
        __half z = __float2half(0.0f);
        g_c[0][i] = 0.0f; g_c[1][i] = 0.0f;
#pragma unroll
        for (int p = 0; p < 3; p++) g_h0[p][i] = z;
#pragma unroll
        for (int p = 0; p < 2; p++) g_h1[p][i] = z;
    }
}

// ---------------- pack gate weights: pc = ((f>>3)<<5)|(g<<3)|(f&7) ----------------
__global__ void k_buildW(const float* __restrict__ wf, const float* __restrict__ wi,
                         const float* __restrict__ wo, const float* __restrict__ wc,
                         const float* __restrict__ bf, const float* __restrict__ bi,
                         const float* __restrict__ bo, const float* __restrict__ bc,
                         int layer) {
    int idx = blockIdx.x * blockDim.x + threadIdx.x;
    if (idx >= G4 * GI) return;
    int pc = idx / GI, k = idx % GI;
    int f = ((pc >> 5) << 3) | (pc & 7);
    int g = (pc >> 3) & 3;
    const float* w = (g == 0) ? wf : (g == 1) ? wi : (g == 2) ? wo : wc;
    g_Wt[layer][idx] = __float2half(w[k * 128 + f]);
    if (k == 0) {
        const float* b = (g == 0) ? bf : (g == 1) ? bi : (g == 2) ? bo : bc;
        g_b4[layer][pc] = b[f];
    }
}

__global__ void k_buildGW(const float* __restrict__ gw, int layer) {
    int idx = blockIdx.x * blockDim.x + threadIdx.x;
    if (idx >= HH * HH) return;
    int n = idx >> 7, k = idx & 127;
    g_gwT[layer][idx] = __float2half(gw[k * 128 + n]);
}

// ================= shared MMA mainloop =================
// 512 threads, 16 warps (4M x 4N of 32x32), tile 128x128, K chunks of 64.
// per-buffer layout: A 16K | B 16K (SW128 swizzled), single fp16 pass
#define BUFSZ 32768u
#define GATE_SMEM (3 * 32768)   // 3-stage
#define GCN_SMEM  (2 * 32768)   // 2-stage

struct Frag { float acc[2][4][4]; };

__device__ __forceinline__ void mma_chunk(uint32_t base, int m0, int n0, int lane, Frag& F) {
    int a_lr = ((lane >> 3) & 1) * 8 + (lane & 7);
    int a_cb = (lane >> 4) * 16;
    int b_lr = (lane >> 4) * 8 + (lane & 7);
    int b_cb = ((lane >> 3) & 1) * 16;
#pragma unroll
    for (int ks = 0; ks < 4; ks++) {
        int kb = ks * 32;
        uint32_t ah[2][4], bh[4][2];
#pragma unroll
        for (int mf = 0; mf < 2; mf++) {
            int row = m0 + mf * 16 + a_lr;
            uint32_t off = (uint32_t)row * 128 + (((uint32_t)(kb + a_cb)) ^ ((row & 7) << 4));
            ldm4(ah[mf], base + off);
        }
#pragma unroll
        for (int np = 0; np < 2; np++) {
            int row = n0 + np * 16 + b_lr;
            uint32_t off = (uint32_t)row * 128 + (((uint32_t)(kb + b_cb)) ^ ((row & 7) << 4));
            uint32_t t[4];
            ldm4(t, base + 16384 + off);
            bh[np * 2][0] = t[0]; bh[np * 2][1] = t[1];
            bh[np * 2 + 1][0] = t[2]; bh[np * 2 + 1][1] = t[3];
        }
#pragma unroll
        for (int mf = 0; mf < 2; mf++)
#pragma unroll
            for (int nf = 0; nf < 4; nf++) mma16816(F.acc[mf][nf], ah[mf], bh[nf]);
    }
}

// ================= GCN GEMM: out = A @ gwT^T  (N=128, K=128, 2 chunks) =================
// BATCH: A = xh (all t), out = g_xw0.  else: A = h0[a], out = g_xw1[b]
template<bool BATCH>
__global__ __launch_bounds__(512) void k_gcn(int a, int b) {
    extern __shared__ char smem[];
    uint32_t sb = smem_u32(smem);
    int tid = threadIdx.x, wid = tid >> 5, lane = tid & 31;
    int bm = blockIdx.x * 128;
    const __half* A = BATCH ? g_xh : g_h0[a];
    const __half* B = g_gwT[BATCH ? 0 : 1];
    float* out = BATCH ? g_xw0 : g_xw1[b];

    auto load_chunk = [&](int c) {
        uint32_t bo = sb + (uint32_t)(c & 1) * BUFSZ;
        int cofs = c * 64;
        for (int i = tid; i < 1024; i += 512) {
            int r = i >> 3, j = i & 7;
            uint32_t so = swz128((uint32_t)r * 128 + j * 16);
            cp16(bo + so,         A + (size_t)(bm + r) * FIN + cofs + j * 8);
            cp16(bo + 16384 + so, B + (size_t)r * HH + cofs + j * 8);
        }
        asm volatile("cp.async.commit_group;" ::: "memory");
    };

    Frag F;
#pragma unroll
    for (int a2 = 0; a2 < 2; a2++)
#pragma unroll
        for (int b2 = 0; b2 < 4; b2++)
#pragma unroll
            for (int r = 0; r < 4; r++) F.acc[a2][b2][r] = 0.0f;

    int m0 = (wid & 3) * 32, n0 = (wid >> 2) * 32;
    load_chunk(0);
    load_chunk(1);
#pragma unroll
    for (int c = 0; c < 2; c++) {
        if (c + 1 < 2) asm volatile("cp.async.wait_group 1;" ::: "memory");
        else           asm volatile("cp.async.wait_group 0;" ::: "memory");
        __syncthreads();
        mma_chunk(sb + (uint32_t)(c & 1) * BUFSZ, m0, n0, lane, F);
        __syncthreads();
    }

    int tq = lane >> 2, tr = (lane & 3) * 2;
#pragma unroll
    for (int mf = 0; mf < 2; mf++)
#pragma unroll
        for (int nf = 0; nf < 4; nf++) {
            int row = bm + m0 + mf * 16 + tq;
            int col = n0 + nf * 8 + tr;
            *(float2*)(out + (size_t)row * HH + col) = make_float2(F.acc[mf][nf][0], F.acc[mf][nf][1]);
            *(float2*)(out + (size_t)(row + 8) * HH + col) = make_float2(F.acc[mf][nf][2], F.acc[mf][nf][3]);
        }
}

// ================= gate GEMM + fused LSTM cell (K=384, 6 chunks, 3-stage) =================
// L==0: A = [x[t] | g0[t] | h0[i0]], writes h0[i1], c0.
// L==1: A = [h0[i0] | g1[i1] | h1[i1^1]], writes h1[i1], c1, hout.   (i1 = t&1)
template<int L>
__global__ __launch_bounds__(512) void k_gate(int t, int i0, int i1) {
    extern __shared__ char smem[];
    uint32_t sb = smem_u32(smem);
    int tid = threadIdx.x, wid = tid >> 5, lane = tid & 31;
    int bm = blockIdx.x * 128, bn = blockIdx.y * 128;
    const __half* B = g_Wt[L];

    auto load_chunk = [&](int c) {
        uint32_t bo = sb + (uint32_t)(c % 3) * BUFSZ;
        const __half* A;
        int half_ = c >> 1;
        if (L == 0) {
            A = (half_ == 0) ? g_xh + (size_t)t * NP * FIN
              : (half_ == 1) ? g_g0 + (size_t)t * NP * HH : g_h0[i0];
        } else {
            A = (half_ == 0) ? g_h0[i0] : (half_ == 1) ? g_g1[i1] : g_h1[i1 ^ 1];
        }
        int cofs = (c & 1) * 64;
        int bk = c * 64;
        for (int i = tid; i < 1024; i += 512) {
            int r = i >> 3, j = i & 7;
            uint32_t so = swz128((uint32_t)r * 128 + j * 16);
            cp16(bo + so,         A + (size_t)(bm + r) * 128 + cofs + j * 8);
            cp16(bo + 16384 + so, B + (size_t)(bn + r) * GI + bk + j * 8);
        }
        asm volatile("cp.async.commit_group;" ::: "memory");
    };

    Frag F;
#pragma unroll
    for (int a = 0; a < 2; a++)
#pragma unroll
        for (int b = 0; b < 4; b++)
#pragma unroll
            for (int r = 0; r < 4; r++) F.acc[a][b][r] = 0.0f;

    int m0 = (wid & 3) * 32, n0 = (wid >> 2) * 32;
    load_chunk(0);
    load_chunk(1);
#pragma unroll
    for (int c = 0; c < 6; c++) {
        if (c + 2 < 6) { load_chunk(c + 2); asm volatile("cp.async.wait_group 2;" ::: "memory"); }
        else if (c + 1 < 6) asm volatile("cp.async.wait_group 1;" ::: "memory");
        else                asm volatile("cp.async.wait_group 0;" ::: "memory");
        __syncthreads();
        mma_chunk(sb + (uint32_t)(c % 3) * BUFSZ, m0, n0, lane, F);
        __syncthreads();
    }

    // fused LSTM pointwise epilogue (gate-interleaved packing: nf == gate)
    int tq = lane >> 2, tr = (lane & 3) * 2;
    int colbase = bn + n0;
    int fb = (colbase >> 5) * 8;
    const float* bias = g_b4[L];
#pragma unroll
    for (int mf = 0; mf < 2; mf++) {
#pragma unroll
        for (int h = 0; h < 2; h++) {
            int row = bm + m0 + mf * 16 + tq + h * 8;
#pragma unroll
            for (int e = 0; e < 2; e++) {
                int col0 = colbase + tr + e;
                float p0 = F.acc[mf][0][2 * h + e] + bias[col0];
                float p1 = F.acc[mf][1][2 * h + e] + bias[col0 + 8];
                float p2 = F.acc[mf][2][2 * h + e] + bias[col0 + 16];
                float p3 = F.acc[mf][3][2 * h + e] + bias[col0 + 24];
                float ft = sigmoidf_(p0), it = sigmoidf_(p1);
                float ot = sigmoidf_(p2), ct = tanhf(p3);
                size_t off = (size_t)row * 128 + fb + tr + e;
                float cn = ft * g_c[L][off] + it * ct;
                g_c[L][off] = cn;
                float hn = ot * tanhf(cn);
                if (L == 0) { g_h0[i1][off] = __float2half(hn); }
                else        { g_h1[i1][off] = __float2half(hn); g_hout[off] = hn; }
            }
        }
    }
}

// ---------------- GCN aggregation + sigmoid -> fp16 ----------------
// warp-per-node, float4 per lane (lane covers features lane*4..lane*4+3).
// upfront: up=1, grid (NN/4, TT), t = blockIdx.y; in-loop: up=0, grid (NN/4), parity q
__global__ __launch_bounds__(128) void k_aggregate(const float* __restrict__ gb, int up, int q) {
    int t = up ? blockIdx.y : 0;
    const float* xw = up ? g_xw0 + (size_t)t * NP * HH : g_xw1[q];
    __half* og = up ? g_g0 + (size_t)t * NP * HH : g_g1[q];
    int w = threadIdx.x >> 5, lane = threadIdx.x & 31;
    int n = blockIdx.x * 4 + w;
    int fc = lane * 4;

    float disn = g_dis[n];
    float s2 = disn * disn;
    float4 v = *(const float4*)(xw + (size_t)n * 128 + fc);
    float4 acc = make_float4(s2 * v.x, s2 * v.y, s2 * v.z, s2 * v.w);

    int p = g_ptr[n], e2 = g_ptr[n + 1];
    for (; p + 4 <= e2; p += 4) {
        int  s0 = g_src[p], s1 = g_src[p + 1], s2i = g_src[p + 2], s3 = g_src[p + 3];
        float w0 = g_wn[p], w1 = g_wn[p + 1], w2 = g_wn[p + 2], w3 = g_wn[p + 3];
        float4 v0 = *(const float4*)(xw + (size_t)s0 * 128 + fc);
        float4 v1 = *(const float4*)(xw + (size_t)s1 * 128 + fc);
        float4 v2 = *(const float4*)(xw + (size_t)s2i * 128 + fc);
        float4 v3 = *(const float4*)(xw + (size_t)s3 * 128 + fc);
        acc.x += w0 * v0.x + w1 * v1.x + w2 * v2.x + w3 * v3.x;
        acc.y += w0 * v0.y + w1 * v1.y + w2 * v2.y + w3 * v3.y;
        acc.z += w0 * v0.z + w1 * v1.z + w2 * v2.z + w3 * v3.z;
        acc.w += w0 * v0.w + w1 * v1.w + w2 * v2.w + w3 * v3.w;
    }
    for (; p < e2; p++) {
        float we = g_wn[p];
        float4 ve = *(const float4*)(xw + (size_t)g_src[p] * 128 + fc);
        acc.x += we * ve.x; acc.y += we * ve.y;
        acc.z += we * ve.z; acc.w += we * ve.w;
    }
    float4 b = *(const float4*)(gb + fc);
    __half2 o0 = __floats2half2_rn(sigmoidf_(acc.x + b.x), sigmoidf_(acc.y + b.y));
    __half2 o1 = __floats2half2_rn(sigmoidf_(acc.z + b.z), sigmoidf_(acc.w + b.w));
    __half2* dst = (__half2*)(og + (size_t)n * 128 + fc);
    dst[0] = o0;
    dst[1] = o1;
}

// ---------------- output projection ----------------
__global__ void k_out(const float* __restrict__ ow, const float* __restrict__ ob,
                      float* __restrict__ out) {
    __shared__ float hs[4][128];
    int r0 = blockIdx.x * 4;
    int tid = threadIdx.x;
    for (int idx = tid; idx < 512; idx += 256) {
        int rr = idx >> 7, kk = idx & 127;
        int n = r0 + rr;
        hs[rr][kk] = (n < NN) ? g_hout[(size_t)n * 128 + kk] : 0.0f;
    }
    __syncthreads();
    int rr = tid >> 6, j = tid & 63;
    float acc = ob[j];
#pragma unroll 8
    for (int k = 0; k < 128; k++) acc += hs[rr][k] * ow[k * 64 + j];
    int n = r0 + rr;
    if (n < NN) out[(size_t)n * 64 + j] = acc;
}

// ---------------- launch (prep/data fork, validated in round 13) ----------------
extern "C" void kernel_launch(void* const* d_in, const int* in_sizes, int n_in,
                              void* d_out, int out_size) {
    const float* x  = (const float*)d_in[0];
    const float* ea = (const float*)d_in[1];
    const int*   ei = (const int*)  d_in[2];
    const float* gw0 = (const float*)d_in[3];
    const float* gb0 = (const float*)d_in[4];
    const float* wf0 = (const float*)d_in[5];
    const float* bf0 = (const float*)d_in[6];
    const float* wi0 = (const float*)d_in[7];
    const float* bi0 = (const float*)d_in[8];
    const float* wo0 = (const float*)d_in[9];
    const float* bo0 = (const float*)d_in[10];
    const float* wc0 = (const float*)d_in[11];
    const float* bc0 = (const float*)d_in[12];
    const float* gw1 = (const float*)d_in[13];
    const float* gb1 = (const float*)d_in[14];
    const float* wf1 = (const float*)d_in[15];
    const float* bf1 = (const float*)d_in[16];
    const float* wi1 = (const float*)d_in[17];
    const float* bi1 = (const float*)d_in[18];
    const float* wo1 = (const float*)d_in[19];
    const float* bo1 = (const float*)d_in[20];
    const float* wc1 = (const float*)d_in[21];
    const float* bc1 = (const float*)d_in[22];
    const float* ow  = (const float*)d_in[23];
    const float* ob  = (const float*)d_in[24];
    float* out = (float*)d_out;

    static cudaStream_t sB = nullptr, sC = nullptr;
    static cudaEvent_t eA[TT], eB[TT], eC[TT], ePre, ePrep, eInit, eEndB, eEndC;
    static bool inited = false;
    if (!inited) {
        cudaStreamCreateWithFlags(&sB, cudaStreamNonBlocking);
        cudaStreamCreateWithFlags(&sC, cudaStreamNonBlocking);
        for (int t = 0; t < TT; t++) {
            cudaEventCreateWithFlags(&eA[t], cudaEventDisableTiming);
            cudaEventCreateWithFlags(&eB[t], cudaEventDisableTiming);
            cudaEventCreateWithFlags(&eC[t], cudaEventDisableTiming);
        }
        cudaEventCreateWithFlags(&ePre, cudaEventDisableTiming);
        cudaEventCreateWithFlags(&ePrep, cudaEventDisableTiming);
        cudaEventCreateWithFlags(&eInit, cudaEventDisableTiming);
        cudaEventCreateWithFlags(&eEndB, cudaEventDisableTiming);
        cudaEventCreateWithFlags(&eEndC, cudaEventDisableTiming);
        cudaFuncSetAttribute(k_gate<0>, cudaFuncAttributeMaxDynamicSharedMemorySize, GATE_SMEM);
        cudaFuncSetAttribute(k_gate<1>, cudaFuncAttributeMaxDynamicSharedMemorySize, GATE_SMEM);
        cudaFuncSetAttribute(k_gcn<true>,  cudaFuncAttributeMaxDynamicSharedMemorySize, GCN_SMEM);
        cudaFuncSetAttribute(k_gcn<false>, cudaFuncAttributeMaxDynamicSharedMemorySize, GCN_SMEM);
        inited = true;
    }

    // fork point for sB's init work
    cudaEventRecord(ePre, 0);

    // ---- stream0: graph prep ----
    k_init_nodes<<<(NN + 255) / 256, 256>>>();
    k_edge_deg<<<EE / 256, 256>>>(ea, ei);
    k_node_prep<<<(NN + 255) / 256, 256>>>();
    k_scan<<<1, 1024>>>();
    k_edge_fill<<<EE / 256, 256>>>(ea, ei);
    cudaEventRecord(ePrep, 0);

    // ---- sB (forked from ePre): transpose + zeros + packs + batched GCN ----
    cudaStreamWaitEvent(sB, ePre, 0);
    k_transpose<<<(NN * FIN + 255) / 256, 256, 0, sB>>>(x);
    {
        int tot = (2 * TT + 2) * (NP - NN) * HH;
        k_zero_pads<<<(tot + 255) / 256, 256, 0, sB>>>();
    }
    k_zero_state<<<((long)NP * HH + 255) / 256, 256, 0, sB>>>();
    k_buildW<<<(G4 * GI + 255) / 256, 256, 0, sB>>>(wf0, wi0, wo0, wc0, bf0, bi0, bo0, bc0, 0);
    k_buildW<<<(G4 * GI + 255) / 256, 256, 0, sB>>>(wf1, wi1, wo1, wc1, bf1, bi1, bo1, bc1, 1);
    k_buildGW<<<(HH * HH + 255) / 256, 256, 0, sB>>>(gw0, 0);
    k_buildGW<<<(HH * HH + 255) / 256, 256, 0, sB>>>(gw1, 1);
    k_gcn<true><<<MT / 128, 512, GCN_SMEM, sB>>>(0, 0);            // xw0 all t
    cudaStreamWaitEvent(sB, ePrep, 0);                             // join graph prep
    k_aggregate<<<dim3(NN / 4, TT), 128, 0, sB>>>(gb0, 1, 0);      // g0 all t
    cudaEventRecord(eInit, sB);

    // stream0 joins init before the loop
    cudaStreamWaitEvent(0, eInit, 0);

    // ---- overlapped time loop ----
    // stream0: gate0 chain; sB: gcn+agg; sC: gate1 chain
    for (int t = 0; t < TT; t++) {
        int q = t & 1;
        int h0w = t % 3;             // gate0 writes h0[h0w]
        int h0r = (t + 2) % 3;       // gate0 reads h0[(t-1)%3]; buffer 2 zeroed for t=0
        if (t >= 3) cudaStreamWaitEvent(0, eC[t - 3], 0);   // h0[h0w] prior readers done
        k_gate<0><<<dim3(NP / 128, 4), 512, GATE_SMEM, 0>>>(t, h0r, h0w);
        cudaEventRecord(eA[t], 0);

        if (t >= 2) cudaStreamWaitEvent(sB, eC[t - 2], 0);  // g1[q]/xw1[q] prior readers done
        cudaStreamWaitEvent(sB, eA[t], 0);
        k_gcn<false><<<NP / 128, 512, GCN_SMEM, sB>>>(h0w, q);
        k_aggregate<<<NN / 4, 128, 0, sB>>>(gb1, 0, q);
        cudaEventRecord(eB[t], sB);

        cudaStreamWaitEvent(sC, eB[t], 0);
        k_gate<1><<<dim3(NP / 128, 4), 512, GATE_SMEM, sC>>>(t, h0w, q);
        cudaEventRecord(eC[t], sC);
    }

    k_out<<<(NN + 3) / 4, 256, 0, sC>>>(ow, ob, out);
    cudaEventRecord(eEndC, sC);
    cudaEventRecord(eEndB, sB);
    cudaStreamWaitEvent(0, eEndB, 0);
    cudaStreamWaitEvent(0, eEndC, 0);
}

// round 17
// speedup vs baseline: 1.4972x; 1.1746x over previous
#include <cuda_runtime.h>
#include <cuda_fp16.h>
#include <math.h>
#include <stdint.h>

#define NN   20000
#define NP   20096      // 157 * 128
#define EE   640000
#define FIN  128
#define HH   128
#define TT   12
#define NOUT 64
#define GI   384
#define G4   512
#define MT   (TT * NP)  // 241152 batched rows

// ---------------- scratch ----------------
__device__ __half g_xh[(size_t)MT * FIN];        // x transposed+rounded, all t
__device__ __half g_g0[(size_t)MT * HH];         // upfront g0 per t
__device__ float  g_xw0[(size_t)MT * HH];        // upfront batched GCN out (fp32)
__device__ __half g_h0[3][(size_t)NP * HH];      // h0 triple buffer (mod 3)
__device__ __half g_h1[2][(size_t)NP * HH];      // h1 parity
__device__ float  g_c[2][(size_t)NP * HH];
__device__ float  g_hout[(size_t)NP * HH];
__device__ float  g_xw1[2][(size_t)NP * HH];     // in-loop gcn out, parity (fp32)
__device__ __half g_g1[2][(size_t)NP * HH];      // in-loop g, parity
__device__ __half g_Wt[2][G4 * GI];      // [pc=512][k=384] gate-interleaved, fp16
__device__ __half g_gwT[2][HH * HH];     // fp16
__device__ float  g_b4[2][G4];           // packed by pc
__device__ float g_deg[NN];
__device__ float g_dis[NN];
__device__ int   g_cnt[NN];
__device__ int   g_cur[NN];
__device__ int   g_ptr[NN + 1];
__device__ int   g_src[EE];
__device__ float g_wn[EE];

__device__ __forceinline__ float sigmoidf_(float x) { return 1.0f / (1.0f + expf(-x)); }
__device__ __forceinline__ uint32_t smem_u32(const void* p) {
    return (uint32_t)__cvta_generic_to_shared(p);
}
__device__ __forceinline__ uint32_t swz128(uint32_t o) { return o ^ ((o >> 3) & 0x70); }
__device__ __forceinline__ void cp16(uint32_t dst, const void* src) {
    asm volatile("cp.async.cg.shared.global [%0], [%1], 16;" :: "r"(dst), "l"(src));
}
__device__ __forceinline__ void ldm4(uint32_t* r, uint32_t addr) {
    asm volatile("ldmatrix.sync.aligned.m8n8.x4.shared.b16 {%0,%1,%2,%3}, [%4];"
                 : "=r"(r[0]), "=r"(r[1]), "=r"(r[2]), "=r"(r[3]) : "r"(addr));
}
__device__ __forceinline__ void mma16816(float* c, const uint32_t* a, const uint32_t* b) {
    asm volatile("mma.sync.aligned.m16n8k16.row.col.f32.f16.f16.f32 "
                 "{%0,%1,%2,%3}, {%4,%5,%6,%7}, {%8,%9}, {%0,%1,%2,%3};"
                 : "+f"(c[0]), "+f"(c[1]), "+f"(c[2]), "+f"(c[3])
                 : "r"(a[0]), "r"(a[1]), "r"(a[2]), "r"(a[3]), "r"(b[0]), "r"(b[1]));
}

// ---------------- graph preprocessing ----------------
__global__ void k_init_nodes() {
    int i = blockIdx.x * blockDim.x + threadIdx.x;
    if (i < NN) { g_deg[i] = 1.0f; g_cnt[i] = 0; }
}
__global__ void k_edge_deg(const float* __restrict__ ea, const int* __restrict__ ei) {
    int e = blockIdx.x * blockDim.x + threadIdx.x;
    if (e < EE) {
        int c = ei[EE + e];
        atomicAdd(&g_deg[c], ea[4 * e + 3]);
        atomicAdd(&g_cnt[c], 1);
    }
}
__global__ void k_node_prep() {
    int i = blockIdx.x * blockDim.x + threadIdx.x;
    if (i < NN) { g_dis[i] = rsqrtf(g_deg[i]); g_cur[i] = 0; }
}
__global__ void k_scan() {
    __shared__ int sh[2][1024];
    __shared__ int carry;
    int tid = threadIdx.x;
    if (tid == 0) carry = 0;
    __syncthreads();
    for (int base = 0; base < NN; base += 1024) {
        int v = (base + tid < NN) ? g_cnt[base + tid] : 0;
        int buf = 0;
        sh[0][tid] = v;
        __syncthreads();
        for (int off = 1; off < 1024; off <<= 1) {
            int val = sh[buf][tid];
            if (tid >= off) val += sh[buf][tid - off];
            sh[buf ^ 1][tid] = val;
            buf ^= 1;
            __syncthreads();
        }
        int incl = sh[buf][tid];
        int c0 = carry;
        if (base + tid < NN) g_ptr[base + tid] = c0 + incl - v;
        __syncthreads();
        if (tid == 1023) carry = c0 + sh[buf][1023];
        __syncthreads();
    }
    if (tid == 0) g_ptr[NN] = carry;
}
__global__ void k_edge_fill(const float* __restrict__ ea, const int* __restrict__ ei) {
    int e = blockIdx.x * blockDim.x + threadIdx.x;
    if (e < EE) {
        int r = ei[e];
        int c = ei[EE + e];
        float w = ea[4 * e + 3];
        int pos = g_ptr[c] + atomicAdd(&g_cur[c], 1);
        g_src[pos] = r;
        g_wn[pos]  = g_dis[r] * w * g_dis[c];
    }
}

// ---------------- input transpose (fp32 -> fp16) ----------------
__global__ void k_transpose(const float* __restrict__ x) {
    long nf = (long)blockIdx.x * blockDim.x + threadIdx.x;
    if (nf >= (long)NN * FIN) return;
    float v[TT];
#pragma unroll
    for (int t = 0; t < TT; t++) v[t] = x[nf * TT + t];
#pragma unroll
    for (int t = 0; t < TT; t++)
        g_xh[(long)t * NP * FIN + nf] = __float2half(v[t]);
}

// slices: s<TT: xh[t] pads; s<2TT: g0[t] pads; s=2TT,2TT+1: g1[parity] pads
__global__ void k_zero_pads() {
    const int padN = (NP - NN) * HH;   // 12288
    int i = blockIdx.x * blockDim.x + threadIdx.x;
    int s = i / padN, r = i % padN;
    if (s >= 2 * TT + 2) return;
    __half z = __float2half(0.0f);
    if (s < TT) {
        g_xh[(long)s * NP * FIN + (long)NN * FIN + r] = z;
    } else if (s < 2 * TT) {
        g_g0[(long)(s - TT) * NP * HH + (long)NN * HH + r] = z;
    } else {
        g_g1[s - 2 * TT][(long)NN * HH + r] = z;
    }
}

__global__ void k_zero_state() {
    long i = (long)blockIdx.x * blockDim.x + threadIdx.x;
    if (i < (long)NP * HH) {
        __half z = __float2half(0.0f);
        g_c[0][i] = 0.0f; g_c[1][i] = 0.0f;
#pragma unroll
        for (int p = 0; p < 3; p++) g_h0[p][i] = z;
#pragma unroll
        for (int p = 0; p < 2; p++) g_h1[p][i] = z;
    }
}

// ---------------- pack gate weights: pc = ((f>>3)<<5)|(g<<3)|(f&7) ----------------
__global__ void k_buildW(const float* __restrict__ wf, const float* __restrict__ wi,
                         const float* __restrict__ wo, const float* __restrict__ wc,
                         const float* __restrict__ bf, const float* __restrict__ bi,
                         const float* __restrict__ bo, const float* __restrict__ bc,
                         int layer) {
    int idx = blockIdx.x * blockDim.x + threadIdx.x;
    if (idx >= G4 * GI) return;
    int pc = idx / GI, k = idx % GI;
    int f = ((pc >> 5) << 3) | (pc & 7);
    int g = (pc >> 3) & 3;
    const float* w = (g == 0) ? wf : (g == 1) ? wi : (g == 2) ? wo : wc;
    g_Wt[layer][idx] = __float2half(w[k * 128 + f]);
    if (k == 0) {
        const float* b = (g == 0) ? bf : (g == 1) ? bi : (g == 2) ? bo : bc;
        g_b4[layer][pc] = b[f];
    }
}

__global__ void k_buildGW(const float* __restrict__ gw, int layer) {
    int idx = blockIdx.x * blockDim.x + threadIdx.x;
    if (idx >= HH * HH) return;
    int n = idx >> 7, k = idx & 127;
    g_gwT[layer][idx] = __float2half(gw[k * 128 + n]);
}

// ================= shared MMA mainloop =================
// 512 threads, 16 warps (4M x 4N of 32x32), tile 128x128, K chunks of 64.
// per-buffer layout: A 16K | B 16K (SW128 swizzled), single fp16 pass
#define BUFSZ 32768u
#define GATE_SMEM (3 * 32768)   // 3-stage
#define GCN_SMEM  (2 * 32768)   // 2-stage

struct Frag { float acc[2][4][4]; };

__device__ __forceinline__ void mma_chunk(uint32_t base, int m0, int n0, int lane, Frag& F) {
    int a_lr = ((lane >> 3) & 1) * 8 + (lane & 7);
    int a_cb = (lane >> 4) * 16;
    int b_lr = (lane >> 4) * 8 + (lane & 7);
    int b_cb = ((lane >> 3) & 1) * 16;
#pragma unroll
    for (int ks = 0; ks < 4; ks++) {
        int kb = ks * 32;
        uint32_t ah[2][4], bh[4][2];
#pragma unroll
        for (int mf = 0; mf < 2; mf++) {
            int row = m0 + mf * 16 + a_lr;
            uint32_t off = (uint32_t)row * 128 + (((uint32_t)(kb + a_cb)) ^ ((row & 7) << 4));
            ldm4(ah[mf], base + off);
        }
#pragma unroll
        for (int np = 0; np < 2; np++) {
            int row = n0 + np * 16 + b_lr;
            uint32_t off = (uint32_t)row * 128 + (((uint32_t)(kb + b_cb)) ^ ((row & 7) << 4));
            uint32_t t[4];
            ldm4(t, base + 16384 + off);
            bh[np * 2][0] = t[0]; bh[np * 2][1] = t[1];
            bh[np * 2 + 1][0] = t[2]; bh[np * 2 + 1][1] = t[3];
        }
#pragma unroll
        for (int mf = 0; mf < 2; mf++)
#pragma unroll
            for (int nf = 0; nf < 4; nf++) mma16816(F.acc[mf][nf], ah[mf], bh[nf]);
    }
}

// ================= GCN GEMM: out = A @ gwT^T  (N=128, K=128, 2 chunks) =================
// BATCH: A = xh (all t), out = g_xw0.  else: A = h0[a], out = g_xw1[b]
template<bool BATCH>
__global__ __launch_bounds__(512, 2) void k_gcn(int a, int b) {
    extern __shared__ char smem[];
    uint32_t sb = smem_u32(smem);
    int tid = threadIdx.x, wid = tid >> 5, lane = tid & 31;
    int bm = blockIdx.x * 128;
    const __half* A = BATCH ? g_xh : g_h0[a];
    const __half* B = g_gwT[BATCH ? 0 : 1];
    float* out = BATCH ? g_xw0 : g_xw1[b];

    auto load_chunk = [&](int c) {
        uint32_t bo = sb + (uint32_t)(c & 1) * BUFSZ;
        int cofs = c * 64;
        for (int i = tid; i < 1024; i += 512) {
            int r = i >> 3, j = i & 7;
            uint32_t so = swz128((uint32_t)r * 128 + j * 16);
            cp16(bo + so,         A + (size_t)(bm + r) * FIN + cofs + j * 8);
            cp16(bo + 16384 + so, B + (size_t)r * HH + cofs + j * 8);
        }
        asm volatile("cp.async.commit_group;" ::: "memory");
    };

    Frag F;
#pragma unroll
    for (int a2 = 0; a2 < 2; a2++)
#pragma unroll
        for (int b2 = 0; b2 < 4; b2++)
#pragma unroll
            for (int r = 0; r < 4; r++) F.acc[a2][b2][r] = 0.0f;

    int m0 = (wid & 3) * 32, n0 = (wid >> 2) * 32;
    load_chunk(0);
    load_chunk(1);
#pragma unroll
    for (int c = 0; c < 2; c++) {
        if (c + 1 < 2) asm volatile("cp.async.wait_group 1;" ::: "memory");
        else           asm volatile("cp.async.wait_group 0;" ::: "memory");
        __syncthreads();
        mma_chunk(sb + (uint32_t)(c & 1) * BUFSZ, m0, n0, lane, F);
        __syncthreads();
    }

    int tq = lane >> 2, tr = (lane & 3) * 2;
#pragma unroll
    for (int mf = 0; mf < 2; mf++)
#pragma unroll
        for (int nf = 0; nf < 4; nf++) {
            int row = bm + m0 + mf * 16 + tq;
            int col = n0 + nf * 8 + tr;
            *(float2*)(out + (size_t)row * HH + col) = make_float2(F.acc[mf][nf][0], F.acc[mf][nf][1]);
            *(float2*)(out + (size_t)(row + 8) * HH + col) = make_float2(F.acc[mf][nf][2], F.acc[mf][nf][3]);
        }
}

// ================= gate GEMM + fused LSTM cell (K=384, 6 chunks, 3-stage) =================
// L==0: A = [x[t] | g0[t] | h0[i0]], writes h0[i1], c0.
// L==1: A = [h0[i0] | g1[i1] | h1[i1^1]], writes h1[i1], c1, hout.   (i1 = t&1)
template<int L>
__global__ __launch_bounds__(512, 2) void k_gate(int t, int i0, int i1) {
    extern __shared__ char smem[];
    uint32_t sb = smem_u32(smem);
    int tid = threadIdx.x, wid = tid >> 5, lane = tid & 31;
    int bm = blockIdx.x * 128, bn = blockIdx.y * 128;
    const __half* B = g_Wt[L];

    auto load_chunk = [&](int c) {
        uint32_t bo = sb + (uint32_t)(c % 3) * BUFSZ;
        const __half* A;
        int half_ = c >> 1;
        if (L == 0) {
            A = (half_ == 0) ? g_xh + (size_t)t * NP * FIN
              : (half_ == 1) ? g_g0 + (size_t)t * NP * HH : g_h0[i0];
        } else {
            A = (half_ == 0) ? g_h0[i0] : (half_ == 1) ? g_g1[i1] : g_h1[i1 ^ 1];
        }
        int cofs = (c & 1) * 64;
        int bk = c * 64;
        for (int i = tid; i < 1024; i += 512) {
            int r = i >> 3, j = i & 7;
            uint32_t so = swz128((uint32_t)r * 128 + j * 16);
            cp16(bo + so,         A + (size_t)(bm + r) * 128 + cofs + j * 8);
            cp16(bo + 16384 + so, B + (size_t)(bn + r) * GI + bk + j * 8);
        }
        asm volatile("cp.async.commit_group;" ::: "memory");
    };

    Frag F;
#pragma unroll
    for (int a = 0; a < 2; a++)
#pragma unroll
        for (int b = 0; b < 4; b++)
#pragma unroll
            for (int r = 0; r < 4; r++) F.acc[a][b][r] = 0.0f;

    int m0 = (wid & 3) * 32, n0 = (wid >> 2) * 32;
    load_chunk(0);
    load_chunk(1);
#pragma unroll
    for (int c = 0; c < 6; c++) {
        if (c + 2 < 6) { load_chunk(c + 2); asm volatile("cp.async.wait_group 2;" ::: "memory"); }
        else if (c + 1 < 6) asm volatile("cp.async.wait_group 1;" ::: "memory");
        else                asm volatile("cp.async.wait_group 0;" ::: "memory");
        __syncthreads();
        mma_chunk(sb + (uint32_t)(c % 3) * BUFSZ, m0, n0, lane, F);
        __syncthreads();
    }

    // fused LSTM pointwise epilogue (gate-interleaved packing: nf == gate)
    int tq = lane >> 2, tr = (lane & 3) * 2;
    int colbase = bn + n0;
    int fb = (colbase >> 5) * 8;
    const float* bias = g_b4[L];
#pragma unroll
    for (int mf = 0; mf < 2; mf++) {
#pragma unroll
        for (int h = 0; h < 2; h++) {
            int row = bm + m0 + mf * 16 + tq + h * 8;
#pragma unroll
            for (int e = 0; e < 2; e++) {
                int col0 = colbase + tr + e;
                float p0 = F.acc[mf][0][2 * h + e] + bias[col0];
                float p1 = F.acc[mf][1][2 * h + e] + bias[col0 + 8];
                float p2 = F.acc[mf][2][2 * h + e] + bias[col0 + 16];
                float p3 = F.acc[mf][3][2 * h + e] + bias[col0 + 24];
                float ft = sigmoidf_(p0), it = sigmoidf_(p1);
                float ot = sigmoidf_(p2), ct = tanhf(p3);
                size_t off = (size_t)row * 128 + fb + tr + e;
                float cn = ft * g_c[L][off] + it * ct;
                g_c[L][off] = cn;
                float hn = ot * tanhf(cn);
                if (L == 0) { g_h0[i1][off] = __float2half(hn); }
                else        { g_h1[i1][off] = __float2half(hn); g_hout[off] = hn; }
            }
        }
    }
}

// ---------------- GCN aggregation + sigmoid -> fp16 ----------------
// warp-per-node, float4 per lane (lane covers features lane*4..lane*4+3).
// upfront: up=1, grid (NN/4, TT), t = blockIdx.y; in-loop: up=0, grid (NN/4), parity q
__global__ __launch_bounds__(128) void k_aggregate(const float* __restrict__ gb, int up, int q) {
    int t = up ? blockIdx.y : 0;
    const float* xw = up ? g_xw0 + (size_t)t * NP * HH : g_xw1[q];
    __half* og = up ? g_g0 + (size_t)t * NP * HH : g_g1[q];
    int w = threadIdx.x >> 5, lane = threadIdx.x & 31;
    int n = blockIdx.x * 4 + w;
    int fc = lane * 4;

    float disn = g_dis[n];
    float s2 = disn * disn;
    float4 v = *(const float4*)(xw + (size_t)n * 128 + fc);
    float4 acc = make_float4(s2 * v.x, s2 * v.y, s2 * v.z, s2 * v.w);

    int p = g_ptr[n], e2 = g_ptr[n + 1];
    for (; p + 4 <= e2; p += 4) {
        int  s0 = g_src[p], s1 = g_src[p + 1], s2i = g_src[p + 2], s3 = g_src[p + 3];
        float w0 = g_wn[p], w1 = g_wn[p + 1], w2 = g_wn[p + 2], w3 = g_wn[p + 3];
        float4 v0 = *(const float4*)(xw + (size_t)s0 * 128 + fc);
        float4 v1 = *(const float4*)(xw + (size_t)s1 * 128 + fc);
        float4 v2 = *(const float4*)(xw + (size_t)s2i * 128 + fc);
        float4 v3 = *(const float4*)(xw + (size_t)s3 * 128 + fc);
        acc.x += w0 * v0.x + w1 * v1.x + w2 * v2.x + w3 * v3.x;
        acc.y += w0 * v0.y + w1 * v1.y + w2 * v2.y + w3 * v3.y;
        acc.z += w0 * v0.z + w1 * v1.z + w2 * v2.z + w3 * v3.z;
        acc.w += w0 * v0.w + w1 * v1.w + w2 * v2.w + w3 * v3.w;
    }
    for (; p < e2; p++) {
        float we = g_wn[p];
        float4 ve = *(const float4*)(xw + (size_t)g_src[p] * 128 + fc);
        acc.x += we * ve.x; acc.y += we * ve.y;
        acc.z += we * ve.z; acc.w += we * ve.w;
    }
    float4 b = *(const float4*)(gb + fc);
    __half2 o0 = __floats2half2_rn(sigmoidf_(acc.x + b.x), sigmoidf_(acc.y + b.y));
    __half2 o1 = __floats2half2_rn(sigmoidf_(acc.z + b.z), sigmoidf_(acc.w + b.w));
    __half2* dst = (__half2*)(og + (size_t)n * 128 + fc);
    dst[0] = o0;
    dst[1] = o1;
}

// ---------------- output projection ----------------
__global__ void k_out(const float* __restrict__ ow, const float* __restrict__ ob,
                      float* __restrict__ out) {
    __shared__ float hs[4][128];
    int r0 = blockIdx.x * 4;
    int tid = threadIdx.x;
    for (int idx = tid; idx < 512; idx += 256) {
        int rr = idx >> 7, kk = idx & 127;
        int n = r0 + rr;
        hs[rr][kk] = (n < NN) ? g_hout[(size_t)n * 128 + kk] : 0.0f;
    }
    __syncthreads();
    int rr = tid >> 6, j = tid & 63;
    float acc = ob[j];
#pragma unroll 8
    for (int k = 0; k < 128; k++) acc += hs[rr][k] * ow[k * 64 + j];
    int n = r0 + rr;
    if (n < NN) out[(size_t)n * 64 + j] = acc;
}

// ---------------- launch (prep/data fork, validated) ----------------
extern "C" void kernel_launch(void* const* d_in, const int* in_sizes, int n_in,
                              void* d_out, int out_size) {
    const float* x  = (const float*)d_in[0];
    const float* ea = (const float*)d_in[1];
    const int*   ei = (const int*)  d_in[2];
    const float* gw0 = (const float*)d_in[3];
    const float* gb0 = (const float*)d_in[4];
    const float* wf0 = (const float*)d_in[5];
    const float* bf0 = (const float*)d_in[6];
    const float* wi0 = (const float*)d_in[7];
    const float* bi0 = (const float*)d_in[8];
    const float* wo0 = (const float*)d_in[9];
    const float* bo0 = (const float*)d_in[10];
    const float* wc0 = (const float*)d_in[11];
    const float* bc0 = (const float*)d_in[12];
    const float* gw1 = (const float*)d_in[13];
    const float* gb1 = (const float*)d_in[14];
    const float* wf1 = (const float*)d_in[15];
    const float* bf1 = (const float*)d_in[16];
    const float* wi1 = (const float*)d_in[17];
    const float* bi1 = (const float*)d_in[18];
    const float* wo1 = (const float*)d_in[19];
    const float* bo1 = (const float*)d_in[20];
    const float* wc1 = (const float*)d_in[21];
    const float* bc1 = (const float*)d_in[22];
    const float* ow  = (const float*)d_in[23];
    const float* ob  = (const float*)d_in[24];
    float* out = (float*)d_out;

    static cudaStream_t sB = nullptr, sC = nullptr;
    static cudaEvent_t eA[TT], eB[TT], eC[TT], ePre, ePrep, eInit, eEndB, eEndC;
    static bool inited = false;
    if (!inited) {
        cudaStreamCreateWithFlags(&sB, cudaStreamNonBlocking);
        cudaStreamCreateWithFlags(&sC, cudaStreamNonBlocking);
        for (int t = 0; t < TT; t++) {
            cudaEventCreateWithFlags(&eA[t], cudaEventDisableTiming);
            cudaEventCreateWithFlags(&eB[t], cudaEventDisableTiming);
            cudaEventCreateWithFlags(&eC[t], cudaEventDisableTiming);
        }
        cudaEventCreateWithFlags(&ePre, cudaEventDisableTiming);
        cudaEventCreateWithFlags(&ePrep, cudaEventDisableTiming);
        cudaEventCreateWithFlags(&eInit, cudaEventDisableTiming);
        cudaEventCreateWithFlags(&eEndB, cudaEventDisableTiming);
        cudaEventCreateWithFlags(&eEndC, cudaEventDisableTiming);
        cudaFuncSetAttribute(k_gate<0>, cudaFuncAttributeMaxDynamicSharedMemorySize, GATE_SMEM);
        cudaFuncSetAttribute(k_gate<1>, cudaFuncAttributeMaxDynamicSharedMemorySize, GATE_SMEM);
        cudaFuncSetAttribute(k_gcn<true>,  cudaFuncAttributeMaxDynamicSharedMemorySize, GCN_SMEM);
        cudaFuncSetAttribute(k_gcn<false>, cudaFuncAttributeMaxDynamicSharedMemorySize, GCN_SMEM);
        inited = true;
    }

    // fork point for sB's init work
    cudaEventRecord(ePre, 0);

    // ---- stream0: graph prep ----
    k_init_nodes<<<(NN + 255) / 256, 256>>>();
    k_edge_deg<<<EE / 256, 256>>>(ea, ei);
    k_node_prep<<<(NN + 255) / 256, 256>>>();
    k_scan<<<1, 1024>>>();
    k_edge_fill<<<EE / 256, 256>>>(ea, ei);
    cudaEventRecord(ePrep, 0);

    // ---- sB (forked from ePre): transpose + zeros + packs + batched GCN ----
    cudaStreamWaitEvent(sB, ePre, 0);
    k_transpose<<<(NN * FIN + 255) / 256, 256, 0, sB>>>(x);
    {
        int tot = (2 * TT + 2) * (NP - NN) * HH;
        k_zero_pads<<<(tot + 255) / 256, 256, 0, sB>>>();
    }
    k_zero_state<<<((long)NP * HH + 255) / 256, 256, 0, sB>>>();
    k_buildW<<<(G4 * GI + 255) / 256, 256, 0, sB>>>(wf0, wi0, wo0, wc0, bf0, bi0, bo0, bc0, 0);
    k_buildW<<<(G4 * GI + 255) / 256, 256, 0, sB>>>(wf1, wi1, wo1, wc1, bf1, bi1, bo1, bc1, 1);
    k_buildGW<<<(HH * HH + 255) / 256, 256, 0, sB>>>(gw0, 0);
    k_buildGW<<<(HH * HH + 255) / 256, 256, 0, sB>>>(gw1, 1);
    k_gcn<true><<<MT / 128, 512, GCN_SMEM, sB>>>(0, 0);            // xw0 all t
    cudaStreamWaitEvent(sB, ePrep, 0);                             // join graph prep
    k_aggregate<<<dim3(NN / 4, TT), 128, 0, sB>>>(gb0, 1, 0);      // g0 all t
    cudaEventRecord(eInit, sB);

    // stream0 joins init before the loop
    cudaStreamWaitEvent(0, eInit, 0);

    // ---- overlapped time loop ----
    // stream0: gate0 chain; sB: gcn+agg; sC: gate1 chain
    for (int t = 0; t < TT; t++) {
        int q = t & 1;
        int h0w = t % 3;             // gate0 writes h0[h0w]
        int h0r = (t + 2) % 3;       // gate0 reads h0[(t-1)%3]; buffer 2 zeroed for t=0
        if (t >= 3) cudaStreamWaitEvent(0, eC[t - 3], 0);   // h0[h0w] prior readers done
        k_gate<0><<<dim3(NP / 128, 4), 512, GATE_SMEM, 0>>>(t, h0r, h0w);
        cudaEventRecord(eA[t], 0);

        if (t >= 2) cudaStreamWaitEvent(sB, eC[t - 2], 0);  // g1[q]/xw1[q] prior readers done
        cudaStreamWaitEvent(sB, eA[t], 0);
        k_gcn<false><<<NP / 128, 512, GCN_SMEM, sB>>>(h0w, q);
        k_aggregate<<<NN / 4, 128, 0, sB>>>(gb1, 0, q);
        cudaEventRecord(eB[t], sB);

        cudaStreamWaitEvent(sC, eB[t], 0);
        k_gate<1><<<dim3(NP / 128, 4), 512, GATE_SMEM, sC>>>(t, h0w, q);
        cudaEventRecord(eC[t], sC);
    }

    k_out<<<(NN + 3) / 4, 256, 0, sC>>>(ow, ob, out);
    cudaEventRecord(eEndC, sC);
    cudaEventRecord(eEndB, sB);
    cudaStreamWaitEvent(0, eEndB, 0);
    cudaStreamWaitEvent(0, eEndC, 0);
}